// round 1
// baseline (speedup 1.0000x reference)
#include <cuda_runtime.h>
#include <math.h>

// Problem constants
#define TT   4096
#define DD   2048
#define HH   16
#define HDD  128
#define QKV_LD 6144   // 3*D

// ---------------------------------------------------------------------------
// Scratch (static __device__ arrays -- allocation-free per harness rules)
// ---------------------------------------------------------------------------
__device__ float g_qkv[(size_t)TT * 3 * DD];          // 96 MB : [T, 3D]
__device__ float g_S  [(size_t)HH * TT * TT];         // 1 GB  : [H, T, T]
__device__ float g_att[(size_t)TT * DD];              // 32 MB : [T, D] (head-interleaved)

// ---------------------------------------------------------------------------
// Generic tiled fp32 GEMM: C = alpha * A @ B (+ mask), batched over blockIdx.z
//   A: row-major M x K, leading dim lda, per-batch stride sAh
//   B: if !TRANSB: row-major K x N (ldb);  if TRANSB: row-major N x K (ldb)
//   C: row-major M x N (ldc)
// BM=BN=128, BK=16, 256 threads, 8x8 per thread.
// All dims are guaranteed multiples of the tile sizes for this problem.
// ---------------------------------------------------------------------------
#define BM 128
#define BN 128
#define BK 16
#define TM 8
#define TN 8

template <bool TRANSB, bool ADDMASK>
__global__ __launch_bounds__(256)
void gemm_kernel(const float* __restrict__ A, long lda, long sAh,
                 const float* __restrict__ B, long ldb, long sBh,
                 float* __restrict__ C, long ldc, long sCh,
                 int M, int N, int K, float alpha,
                 const float* __restrict__ mask, long ldm)
{
    __shared__ float As[BK][BM];
    __shared__ float Bs[BK][BN];

    const int h = blockIdx.z;
    A += (long)h * sAh;
    B += (long)h * sBh;
    C += (long)h * sCh;

    const int bm = blockIdx.y * BM;
    const int bn = blockIdx.x * BN;
    const int tid = threadIdx.x;
    const int tx = tid & 15;          // 0..15 -> N
    const int ty = tid >> 4;          // 0..15 -> M

    float acc[TM][TN];
#pragma unroll
    for (int i = 0; i < TM; i++)
#pragma unroll
        for (int j = 0; j < TN; j++) acc[i][j] = 0.0f;

    for (int k0 = 0; k0 < K; k0 += BK) {
        // ---- load A tile (BM x BK), store transposed As[k][m] ----
#pragma unroll
        for (int r = 0; r < 2; r++) {
            int i   = tid + r * 256;          // 0..511 float4 slots
            int row = i >> 2;                 // 0..127
            int c4  = i & 3;                  // 0..3  (k chunk of 4)
            float4 v = *(const float4*)&A[(long)(bm + row) * lda + k0 + c4 * 4];
            As[c4 * 4 + 0][row] = v.x;
            As[c4 * 4 + 1][row] = v.y;
            As[c4 * 4 + 2][row] = v.z;
            As[c4 * 4 + 3][row] = v.w;
        }
        // ---- load B tile ----
        if (TRANSB) {
            // B is N x K; want Bs[k][n] = B[n][k]
#pragma unroll
            for (int r = 0; r < 2; r++) {
                int i   = tid + r * 256;
                int row = i >> 2;             // n offset 0..127
                int c4  = i & 3;
                float4 v = *(const float4*)&B[(long)(bn + row) * ldb + k0 + c4 * 4];
                Bs[c4 * 4 + 0][row] = v.x;
                Bs[c4 * 4 + 1][row] = v.y;
                Bs[c4 * 4 + 2][row] = v.z;
                Bs[c4 * 4 + 3][row] = v.w;
            }
        } else {
            // B is K x N; Bs[k][n] = B[k][n]
#pragma unroll
            for (int r = 0; r < 2; r++) {
                int i  = tid + r * 256;
                int kk = i >> 5;              // 0..15
                int c  = i & 31;              // 0..31 float4 along n
                float4 v = *(const float4*)&B[(long)(k0 + kk) * ldb + bn + c * 4];
                *(float4*)&Bs[kk][c * 4] = v;
            }
        }
        __syncthreads();

        // ---- compute ----
#pragma unroll
        for (int k = 0; k < BK; k++) {
            float4 a0 = *(const float4*)&As[k][ty * TM];
            float4 a1 = *(const float4*)&As[k][ty * TM + 4];
            float4 b0 = *(const float4*)&Bs[k][tx * TN];
            float4 b1 = *(const float4*)&Bs[k][tx * TN + 4];
            float a[TM] = {a0.x, a0.y, a0.z, a0.w, a1.x, a1.y, a1.z, a1.w};
            float b[TN] = {b0.x, b0.y, b0.z, b0.w, b1.x, b1.y, b1.z, b1.w};
#pragma unroll
            for (int i = 0; i < TM; i++)
#pragma unroll
                for (int j = 0; j < TN; j++)
                    acc[i][j] = fmaf(a[i], b[j], acc[i][j]);
        }
        __syncthreads();
    }

    // ---- epilogue ----
#pragma unroll
    for (int i = 0; i < TM; i++) {
        long row = bm + ty * TM + i;
#pragma unroll
        for (int j = 0; j < TN; j += 4) {
            long col = bn + tx * TN + j;
            float4 v;
            v.x = alpha * acc[i][j + 0];
            v.y = alpha * acc[i][j + 1];
            v.z = alpha * acc[i][j + 2];
            v.w = alpha * acc[i][j + 3];
            if (ADDMASK) {
                float4 m = *(const float4*)&mask[row * ldm + col];
                v.x += m.x; v.y += m.y; v.z += m.z; v.w += m.w;
            }
            *(float4*)&C[row * ldc + col] = v;
        }
    }
}

// ---------------------------------------------------------------------------
// L2-normalize q and k head vectors (128 dims) in place inside g_qkv.
// One warp per vector; 2*T*H = 131072 vectors.
// ---------------------------------------------------------------------------
__global__ __launch_bounds__(256)
void l2norm_kernel(float* __restrict__ qkv)
{
    int gwarp = (blockIdx.x * blockDim.x + threadIdx.x) >> 5;
    int lane  = threadIdx.x & 31;
    if (gwarp >= 2 * TT * HH) return;
    int part = gwarp / (TT * HH);       // 0 = q, 1 = k
    int rem  = gwarp % (TT * HH);
    int t = rem / HH;
    int h = rem % HH;
    float* base = qkv + (long)t * QKV_LD + (long)part * DD + (long)h * HDD;

    float4 v = *(float4*)&base[lane * 4];
    float ss = v.x * v.x + v.y * v.y + v.z * v.z + v.w * v.w;
#pragma unroll
    for (int o = 16; o; o >>= 1) ss += __shfl_xor_sync(0xFFFFFFFFu, ss, o);
    float nrm = sqrtf(ss);
    float s = 1.0f / fmaxf(nrm, 1e-12f);
    v.x *= s; v.y *= s; v.z *= s; v.w *= s;
    *(float4*)&base[lane * 4] = v;
}

// ---------------------------------------------------------------------------
// Row softmax over S: one block (256 threads) per (head, row); row length T.
// ---------------------------------------------------------------------------
__global__ __launch_bounds__(256)
void softmax_kernel(float* __restrict__ S)
{
    float* row = S + ((size_t)blockIdx.y * TT + blockIdx.x) * TT;
    const int tid = threadIdx.x;
    __shared__ float red[8];

    float4 v[4];
    float m = -INFINITY;
#pragma unroll
    for (int r = 0; r < 4; r++) {
        v[r] = *(float4*)&row[tid * 4 + r * 1024];
        m = fmaxf(m, fmaxf(fmaxf(v[r].x, v[r].y), fmaxf(v[r].z, v[r].w)));
    }
    // block max
#pragma unroll
    for (int o = 16; o; o >>= 1) m = fmaxf(m, __shfl_xor_sync(0xFFFFFFFFu, m, o));
    if ((tid & 31) == 0) red[tid >> 5] = m;
    __syncthreads();
    if (tid < 32) {
        float t = (tid < 8) ? red[tid] : -INFINITY;
#pragma unroll
        for (int o = 4; o; o >>= 1) t = fmaxf(t, __shfl_xor_sync(0xFFFFFFFFu, t, o));
        if (tid == 0) red[0] = t;
    }
    __syncthreads();
    m = red[0];
    __syncthreads();

    float s = 0.0f;
#pragma unroll
    for (int r = 0; r < 4; r++) {
        v[r].x = __expf(v[r].x - m);
        v[r].y = __expf(v[r].y - m);
        v[r].z = __expf(v[r].z - m);
        v[r].w = __expf(v[r].w - m);
        s += v[r].x + v[r].y + v[r].z + v[r].w;
    }
#pragma unroll
    for (int o = 16; o; o >>= 1) s += __shfl_xor_sync(0xFFFFFFFFu, s, o);
    if ((tid & 31) == 0) red[tid >> 5] = s;
    __syncthreads();
    if (tid < 32) {
        float t = (tid < 8) ? red[tid] : 0.0f;
#pragma unroll
        for (int o = 4; o; o >>= 1) t += __shfl_xor_sync(0xFFFFFFFFu, t, o);
        if (tid == 0) red[0] = t;
    }
    __syncthreads();
    float inv = 1.0f / red[0];
#pragma unroll
    for (int r = 0; r < 4; r++) {
        v[r].x *= inv; v[r].y *= inv; v[r].z *= inv; v[r].w *= inv;
        *(float4*)&row[tid * 4 + r * 1024] = v[r];
    }
}

// ---------------------------------------------------------------------------
// Launch
// ---------------------------------------------------------------------------
extern "C" void kernel_launch(void* const* d_in, const int* in_sizes, int n_in,
                              void* d_out, int out_size)
{
    const float* x    = (const float*)d_in[0];   // [T, D]
    const float* mask = (const float*)d_in[1];   // [T, T]
    const float* Wqkv = (const float*)d_in[2];   // [D, 3D]
    const float* Wout = (const float*)d_in[3];   // [D, D]
    float* out = (float*)d_out;                  // [T, D]

    float *qkv, *S, *att;
    cudaGetSymbolAddress((void**)&qkv, g_qkv);
    cudaGetSymbolAddress((void**)&S,   g_S);
    cudaGetSymbolAddress((void**)&att, g_att);

    const float scale = 0.08838834764831845f;  // 1/sqrt(128)
    dim3 blk(256);

    // 1) qkv = x @ W_qkv      (4096 x 2048) @ (2048 x 6144)
    gemm_kernel<false, false><<<dim3(QKV_LD / BN, TT / BM, 1), blk>>>(
        x, DD, 0, Wqkv, QKV_LD, 0, qkv, QKV_LD, 0,
        TT, QKV_LD, DD, 1.0f, nullptr, 0);

    // 2) L2-normalize q, k per (t, h) over 128 dims (in place)
    l2norm_kernel<<<(2 * TT * HH) / 8, blk>>>(qkv);

    // 3) S_h = scale * Q_h @ K_h^T + mask   (batched over 16 heads)
    gemm_kernel<true, true><<<dim3(TT / BN, TT / BM, HH), blk>>>(
        qkv, QKV_LD, HDD,                 // A = Q_h : [T,128], lda=6144, head stride 128
        qkv + DD, QKV_LD, HDD,            // B = K_h : [T,128] accessed transposed
        S, TT, (long)TT * TT,             // C = S_h : [T,T]
        TT, TT, HDD, scale, mask, TT);

    // 4) softmax over last dim of S
    softmax_kernel<<<dim3(TT, HH), blk>>>(S);

    // 5) att_h = P_h @ V_h   (batched)  -> g_att laid out [T, H, HD] = [T, D]
    gemm_kernel<false, false><<<dim3(HDD / BN, TT / BM, HH), blk>>>(
        S, TT, (long)TT * TT,             // A = P_h : [T,T]
        qkv + 2 * DD, QKV_LD, HDD,        // B = V_h : [T,128] (k-major rows)
        att, DD, HDD,                     // C : head h at column offset h*128
        TT, HDD, TT, 1.0f, nullptr, 0);

    // 6) out = att @ W_out   (4096 x 2048) @ (2048 x 2048)
    gemm_kernel<false, false><<<dim3(DD / BN, TT / BM, 1), blk>>>(
        att, DD, 0, Wout, DD, 0, out, DD, 0,
        TT, DD, DD, 1.0f, nullptr, 0);
}

// round 5
// speedup vs baseline: 2.1957x; 2.1957x over previous
#include <cuda_runtime.h>
#include <cuda_bf16.h>
#include <stdint.h>
#include <math.h>

// Problem constants
#define TT   4096
#define DD   2048
#define HH   16
#define HDD  128
#define D3   6144   // 3*D

typedef __nv_bfloat16 bf16;

// ---------------------------------------------------------------------------
// Scratch (__device__ globals -- allocation-free per harness rules). ~1.38 GB.
// ---------------------------------------------------------------------------
#define ALGN __align__(256)
__device__ ALGN bf16  g_xh [(size_t)TT*DD];
__device__ ALGN bf16  g_xl [(size_t)TT*DD];
__device__ ALGN bf16  g_wqh[(size_t)D3*DD];
__device__ ALGN bf16  g_wql[(size_t)D3*DD];
__device__ ALGN bf16  g_woh[(size_t)DD*DD];
__device__ ALGN bf16  g_wol[(size_t)DD*DD];
__device__ ALGN float g_qkv[(size_t)TT*D3];
__device__ ALGN bf16  g_qh [(size_t)HH*TT*HDD];
__device__ ALGN bf16  g_ql [(size_t)HH*TT*HDD];
__device__ ALGN bf16  g_kh [(size_t)HH*TT*HDD];
__device__ ALGN bf16  g_kl [(size_t)HH*TT*HDD];
__device__ ALGN bf16  g_vth[(size_t)HH*HDD*TT];
__device__ ALGN bf16  g_vtl[(size_t)HH*HDD*TT];
__device__ ALGN float g_S  [(size_t)HH*TT*TT];   // fp32 scores; softmax rewrites
                                                 // each row in place as bf16
                                                 // [hi x 4096 | lo x 4096]
__device__ ALGN float g_att[(size_t)TT*DD];
__device__ ALGN bf16  g_ah [(size_t)TT*DD];
__device__ ALGN bf16  g_al [(size_t)TT*DD];

// ---------------------------------------------------------------------------
// Helpers
// ---------------------------------------------------------------------------
__device__ __forceinline__ uint32_t smem_u32(const void* p) {
    uint32_t a;
    asm("{ .reg .u64 t; cvta.to.shared.u64 t, %1; cvt.u32.u64 %0, t; }" : "=r"(a) : "l"(p));
    return a;
}
__device__ __forceinline__ void split2(float v, bf16& h, bf16& l) {
    h = __float2bfloat16_rn(v);
    l = __float2bfloat16_rn(v - __bfloat162float(h));
}

#define LDSM4(r, addr) \
    asm volatile("ldmatrix.sync.aligned.m8n8.x4.shared.b16 {%0,%1,%2,%3}, [%4];" \
        : "=r"((r)[0]), "=r"((r)[1]), "=r"((r)[2]), "=r"((r)[3]) : "r"(addr))
#define LDSM2(r, addr) \
    asm volatile("ldmatrix.sync.aligned.m8n8.x2.shared.b16 {%0,%1}, [%2];" \
        : "=r"((r)[0]), "=r"((r)[1]) : "r"(addr))
#define MMA(acc, A, B) \
    asm volatile("mma.sync.aligned.m16n8k16.row.col.f32.bf16.bf16.f32 " \
        "{%0,%1,%2,%3}, {%4,%5,%6,%7}, {%8,%9}, {%0,%1,%2,%3};" \
        : "+f"((acc)[0]), "+f"((acc)[1]), "+f"((acc)[2]), "+f"((acc)[3]) \
        : "r"((A)[0]), "r"((A)[1]), "r"((A)[2]), "r"((A)[3]), \
          "r"((B)[0]), "r"((B)[1]))

__device__ __forceinline__ void cpa(uint32_t s, const bf16* g) {
    asm volatile("cp.async.cg.shared.global [%0], [%1], 16;" :: "r"(s), "l"(g));
}
#define CP_COMMIT asm volatile("cp.async.commit_group;" ::: "memory")
#define CP_WAIT1  asm volatile("cp.async.wait_group 1;"  ::: "memory")
#define CP_WAIT0  asm volatile("cp.async.wait_group 0;"  ::: "memory")

// ---------------------------------------------------------------------------
// bf16-split HMMA GEMM: C[M,N] = alpha * (A @ B^T) (+ mask)
//   A: hi/lo bf16, [M, K] K-major (row stride lda elems), per-batch stride sA
//   B: hi/lo bf16, [N, K] K-major (row stride ldb), per-batch stride sB
//   C: fp32 [M, N] (ldc, sC)
// Block tile 128x128, BK=32, 8 warps (2m x 4n; 64x32 per warp),
// cp.async 2-stage double buffer.  smem row stride = 40 bf16 (80 B).
// ---------------------------------------------------------------------------
#define ROWB  80          // smem bytes per row (32 bf16 + 8 pad)
#define TILB  10240       // one 128-row tile (128 * 80)
#define STGB  40960       // 4 tiles (Ah, Al, Bh, Bl)
#define SMEM_TOT (2 * STGB)

__device__ __forceinline__ void stage_load(
    const bf16* __restrict__ Ah, const bf16* __restrict__ Al, long lda,
    const bf16* __restrict__ Bh, const bf16* __restrict__ Bl, long ldb,
    int bm, int bn, int k0, uint32_t sb, int tid)
{
#pragma unroll
    for (int rep = 0; rep < 2; rep++) {
        int ci  = tid + rep * 256;
        int row = ci >> 2, c = ci & 3;
        uint32_t so = row * ROWB + c * 16;
        size_t ga = (size_t)(bm + row) * lda + k0 + c * 8;
        size_t gb = (size_t)(bn + row) * ldb + k0 + c * 8;
        cpa(sb + so,            Ah + ga);
        cpa(sb + TILB + so,     Al + ga);
        cpa(sb + 2 * TILB + so, Bh + gb);
        cpa(sb + 3 * TILB + so, Bl + gb);
    }
}

template <bool ADDMASK>
__global__ __launch_bounds__(256)
void gemm_bf16(const bf16* __restrict__ Ah, const bf16* __restrict__ Al, long lda, long sA,
               const bf16* __restrict__ Bh, const bf16* __restrict__ Bl, long ldb, long sB,
               float* __restrict__ C, long ldc, long sC,
               int K, float alpha, const float* __restrict__ mask, long ldm)
{
    extern __shared__ char smdyn[];
    const uint32_t sbase = smem_u32(smdyn);
    const int tid = threadIdx.x, lane = tid & 31, wid = tid >> 5;
    const int wm = wid >> 2, wn = wid & 3;          // 2 x 4 warp grid

    const int h = blockIdx.z;
    Ah += (size_t)h * sA;  Al += (size_t)h * sA;
    Bh += (size_t)h * sB;  Bl += (size_t)h * sB;
    C  += (size_t)h * sC;
    const int bm = blockIdx.y * 128, bn = blockIdx.x * 128;

    float acc[4][4][4];
#pragma unroll
    for (int i = 0; i < 4; i++)
#pragma unroll
        for (int j = 0; j < 4; j++)
#pragma unroll
            for (int r = 0; r < 4; r++) acc[i][j][r] = 0.0f;

    stage_load(Ah, Al, lda, Bh, Bl, ldb, bm, bn, 0, sbase, tid);
    CP_COMMIT;

    const int NC = K >> 5;
    for (int c = 0; c < NC; c++) {
        if (c + 1 < NC) {
            stage_load(Ah, Al, lda, Bh, Bl, ldb, bm, bn, (c + 1) << 5,
                       sbase + ((c + 1) & 1) * STGB, tid);
            CP_COMMIT;
            CP_WAIT1;
        } else {
            CP_WAIT0;
        }
        __syncthreads();

        const uint32_t ab = sbase + (c & 1) * STGB;
#pragma unroll
        for (int ks = 0; ks < 2; ks++) {
            const int kb = ks * 32;   // 16 bf16 = 32 bytes
            uint32_t A_h[4][4], A_l[4][4], B_h[4][2], B_l[4][2];
#pragma unroll
            for (int mt = 0; mt < 4; mt++) {
                uint32_t ra = ab + (wm * 64 + mt * 16 + (lane & 15)) * ROWB
                                 + kb + (lane >> 4) * 16;
                LDSM4(A_h[mt], ra);
                LDSM4(A_l[mt], ra + TILB);
            }
#pragma unroll
            for (int nt = 0; nt < 4; nt++) {
                uint32_t rb = ab + 2 * TILB
                                 + (wn * 32 + nt * 8 + (lane & 7)) * ROWB
                                 + kb + ((lane >> 3) & 1) * 16;
                LDSM2(B_h[nt], rb);
                LDSM2(B_l[nt], rb + TILB);
            }
#pragma unroll
            for (int mt = 0; mt < 4; mt++)
#pragma unroll
                for (int nt = 0; nt < 4; nt++) {
                    MMA(acc[mt][nt], A_h[mt], B_h[nt]);
                    MMA(acc[mt][nt], A_h[mt], B_l[nt]);
                    MMA(acc[mt][nt], A_l[mt], B_h[nt]);
                }
        }
        __syncthreads();
    }

    // Epilogue: c0,c1 at (r, c..c+1); c2,c3 at (r+8, c..c+1)
    const int rw = bm + wm * 64 + (lane >> 2);
    const int cw = bn + wn * 32 + (lane & 3) * 2;
#pragma unroll
    for (int mt = 0; mt < 4; mt++) {
#pragma unroll
        for (int nt = 0; nt < 4; nt++) {
            size_t r0 = rw + mt * 16;
            size_t c0 = cw + nt * 8;
            float2 v0 = make_float2(alpha * acc[mt][nt][0], alpha * acc[mt][nt][1]);
            float2 v1 = make_float2(alpha * acc[mt][nt][2], alpha * acc[mt][nt][3]);
            if (ADDMASK) {
                float2 m0 = *(const float2*)&mask[r0 * ldm + c0];
                float2 m1 = *(const float2*)&mask[(r0 + 8) * ldm + c0];
                v0.x += m0.x; v0.y += m0.y;
                v1.x += m1.x; v1.y += m1.y;
            }
            *(float2*)&C[r0 * ldc + c0] = v0;
            *(float2*)&C[(r0 + 8) * ldc + c0] = v1;
        }
    }
}

// ---------------------------------------------------------------------------
// Elementwise split: fp32 -> (hi, lo) bf16. One float4 per thread.
// ---------------------------------------------------------------------------
__global__ __launch_bounds__(256)
void split_arr(const float* __restrict__ src, bf16* __restrict__ oh, bf16* __restrict__ ol)
{
    size_t i = ((size_t)blockIdx.x * 256 + threadIdx.x) * 4;
    float4 v = *(const float4*)&src[i];
    bf16 h0, l0, h1, l1, h2, l2, h3, l3;
    split2(v.x, h0, l0); split2(v.y, h1, l1); split2(v.z, h2, l2); split2(v.w, h3, l3);
    __nv_bfloat162* ph = (__nv_bfloat162*)&oh[i];
    __nv_bfloat162* pl = (__nv_bfloat162*)&ol[i];
    ph[0] = __nv_bfloat162(h0, h1); ph[1] = __nv_bfloat162(h2, h3);
    pl[0] = __nv_bfloat162(l0, l1); pl[1] = __nv_bfloat162(l2, l3);
}

// ---------------------------------------------------------------------------
// Weight transpose + split: W[K,N] fp32 -> WT hi/lo [N,K] bf16
// ---------------------------------------------------------------------------
__global__ __launch_bounds__(256)
void transpose_split(const float* __restrict__ W, int K, int N,
                     bf16* __restrict__ Th, bf16* __restrict__ Tl)
{
    __shared__ float tile[32][33];
    const int n0 = blockIdx.x * 32, k0 = blockIdx.y * 32;
    const int tx = threadIdx.x, ty = threadIdx.y;   // 32 x 8
#pragma unroll
    for (int j = 0; j < 4; j++)
        tile[ty + j * 8][tx] = W[(size_t)(k0 + ty + j * 8) * N + n0 + tx];
    __syncthreads();
#pragma unroll
    for (int j = 0; j < 4; j++) {
        float v = tile[tx][ty + j * 8];
        bf16 h, l; split2(v, h, l);
        size_t o = (size_t)(n0 + ty + j * 8) * K + k0 + tx;
        Th[o] = h; Tl[o] = l;
    }
}

// ---------------------------------------------------------------------------
// L2-normalize q,k vectors (128 dims) and split into per-head [H][T][128]
// One warp per (part, t, h) vector.
// ---------------------------------------------------------------------------
__global__ __launch_bounds__(256)
void l2norm_split(const float* __restrict__ qkv,
                  bf16* __restrict__ qh, bf16* __restrict__ ql,
                  bf16* __restrict__ kh, bf16* __restrict__ kl)
{
    int gw = (blockIdx.x * 256 + threadIdx.x) >> 5;
    int lane = threadIdx.x & 31;
    int part = gw / (TT * HH);
    int rem  = gw % (TT * HH);
    int t = rem / HH, h = rem % HH;
    const float* src = qkv + (size_t)t * D3 + part * DD + h * HDD;
    float4 v = *(const float4*)&src[lane * 4];
    float ss = v.x * v.x + v.y * v.y + v.z * v.z + v.w * v.w;
#pragma unroll
    for (int o = 16; o; o >>= 1) ss += __shfl_xor_sync(0xFFFFFFFFu, ss, o);
    float s = 1.0f / fmaxf(sqrtf(ss), 1e-12f);

    size_t o = ((size_t)h * TT + t) * HDD + lane * 4;
    bf16* dh = (part == 0 ? qh : kh) + o;
    bf16* dl = (part == 0 ? ql : kl) + o;
    bf16 h0, l0, h1, l1, h2, l2, h3, l3;
    split2(v.x * s, h0, l0); split2(v.y * s, h1, l1);
    split2(v.z * s, h2, l2); split2(v.w * s, h3, l3);
    ((__nv_bfloat162*)dh)[0] = __nv_bfloat162(h0, h1);
    ((__nv_bfloat162*)dh)[1] = __nv_bfloat162(h2, h3);
    ((__nv_bfloat162*)dl)[0] = __nv_bfloat162(l0, l1);
    ((__nv_bfloat162*)dl)[1] = __nv_bfloat162(l2, l3);
}

// ---------------------------------------------------------------------------
// V transpose + split: qkv[t][2D + h*128 + d] -> VT hi/lo [h][d][t]
// ---------------------------------------------------------------------------
__global__ __launch_bounds__(256)
void vtrans_split(const float* __restrict__ qkv,
                  bf16* __restrict__ vth, bf16* __restrict__ vtl)
{
    __shared__ float tile[32][33];
    const int h = blockIdx.z;
    const int t0 = blockIdx.x * 32, d0 = blockIdx.y * 32;
    const int tx = threadIdx.x, ty = threadIdx.y;   // 32 x 8
#pragma unroll
    for (int j = 0; j < 4; j++)
        tile[ty + j * 8][tx] = qkv[(size_t)(t0 + ty + j * 8) * D3 + 2 * DD + h * HDD + d0 + tx];
    __syncthreads();
#pragma unroll
    for (int j = 0; j < 4; j++) {
        float v = tile[tx][ty + j * 8];
        bf16 hh, ll; split2(v, hh, ll);
        size_t o = ((size_t)h * HDD + d0 + ty + j * 8) * TT + t0 + tx;
        vth[o] = hh; vtl[o] = ll;
    }
}

// ---------------------------------------------------------------------------
// Row softmax over S, IN PLACE: reads fp32 row (4096), writes the same 16KB
// as [4096 x bf16 hi | 4096 x bf16 lo]. One block (256 threads) per (h, row).
// ---------------------------------------------------------------------------
__global__ __launch_bounds__(256)
void softmax_split_inplace(float* __restrict__ S)
{
    size_t base = ((size_t)blockIdx.y * TT + blockIdx.x) * TT;
    float* row = S + base;
    const int tid = threadIdx.x;
    __shared__ float red[8];

    float4 v[4];
    float m = -INFINITY;
#pragma unroll
    for (int r = 0; r < 4; r++) {
        v[r] = *(const float4*)&row[tid * 4 + r * 1024];
        m = fmaxf(m, fmaxf(fmaxf(v[r].x, v[r].y), fmaxf(v[r].z, v[r].w)));
    }
#pragma unroll
    for (int o = 16; o; o >>= 1) m = fmaxf(m, __shfl_xor_sync(0xFFFFFFFFu, m, o));
    if ((tid & 31) == 0) red[tid >> 5] = m;
    __syncthreads();
    if (tid < 32) {
        float t = (tid < 8) ? red[tid] : -INFINITY;
#pragma unroll
        for (int o = 4; o; o >>= 1) t = fmaxf(t, __shfl_xor_sync(0xFFFFFFFFu, t, o));
        if (tid == 0) red[0] = t;
    }
    __syncthreads();
    m = red[0];
    __syncthreads();

    float s = 0.0f;
#pragma unroll
    for (int r = 0; r < 4; r++) {
        v[r].x = __expf(v[r].x - m); v[r].y = __expf(v[r].y - m);
        v[r].z = __expf(v[r].z - m); v[r].w = __expf(v[r].w - m);
        s += v[r].x + v[r].y + v[r].z + v[r].w;
    }
#pragma unroll
    for (int o = 16; o; o >>= 1) s += __shfl_xor_sync(0xFFFFFFFFu, s, o);
    if ((tid & 31) == 0) red[tid >> 5] = s;
    __syncthreads();
    if (tid < 32) {
        float t = (tid < 8) ? red[tid] : 0.0f;
#pragma unroll
        for (int o = 4; o; o >>= 1) t += __shfl_xor_sync(0xFFFFFFFFu, t, o);
        if (tid == 0) red[0] = t;
    }
    __syncthreads();
    float inv = 1.0f / red[0];

    __syncthreads();
    bf16* Ph = (bf16*)row;            // elements 0..4095
    bf16* Pl = (bf16*)row + TT;       // elements 4096..8191
#pragma unroll
    for (int r = 0; r < 4; r++) {
        int o = tid * 4 + r * 1024;
        bf16 h0, l0, h1, l1, h2, l2, h3, l3;
        split2(v[r].x * inv, h0, l0); split2(v[r].y * inv, h1, l1);
        split2(v[r].z * inv, h2, l2); split2(v[r].w * inv, h3, l3);
        ((__nv_bfloat162*)&Ph[o])[0] = __nv_bfloat162(h0, h1);
        ((__nv_bfloat162*)&Ph[o])[1] = __nv_bfloat162(h2, h3);
        ((__nv_bfloat162*)&Pl[o])[0] = __nv_bfloat162(l0, l1);
        ((__nv_bfloat162*)&Pl[o])[1] = __nv_bfloat162(l2, l3);
    }
}

// ---------------------------------------------------------------------------
// Launch
// ---------------------------------------------------------------------------
extern "C" void kernel_launch(void* const* d_in, const int* in_sizes, int n_in,
                              void* d_out, int out_size)
{
    const float* x    = (const float*)d_in[0];   // [T, D]
    const float* mask = (const float*)d_in[1];   // [T, T]
    const float* Wqkv = (const float*)d_in[2];   // [D, 3D]
    const float* Wout = (const float*)d_in[3];   // [D, D]
    float* out = (float*)d_out;                  // [T, D]

    float *qkv, *S, *att;
    bf16 *xh, *xl, *wqh, *wql, *woh, *wol, *qh, *ql, *kh, *kl, *vth, *vtl, *ah, *al;
    cudaGetSymbolAddress((void**)&qkv, g_qkv);
    cudaGetSymbolAddress((void**)&S,   g_S);
    cudaGetSymbolAddress((void**)&att, g_att);
    cudaGetSymbolAddress((void**)&xh,  g_xh);   cudaGetSymbolAddress((void**)&xl,  g_xl);
    cudaGetSymbolAddress((void**)&wqh, g_wqh);  cudaGetSymbolAddress((void**)&wql, g_wql);
    cudaGetSymbolAddress((void**)&woh, g_woh);  cudaGetSymbolAddress((void**)&wol, g_wol);
    cudaGetSymbolAddress((void**)&qh,  g_qh);   cudaGetSymbolAddress((void**)&ql,  g_ql);
    cudaGetSymbolAddress((void**)&kh,  g_kh);   cudaGetSymbolAddress((void**)&kl,  g_kl);
    cudaGetSymbolAddress((void**)&vth, g_vth);  cudaGetSymbolAddress((void**)&vtl, g_vtl);
    cudaGetSymbolAddress((void**)&ah,  g_ah);   cudaGetSymbolAddress((void**)&al,  g_al);

    cudaFuncSetAttribute(gemm_bf16<false>, cudaFuncAttributeMaxDynamicSharedMemorySize, SMEM_TOT);
    cudaFuncSetAttribute(gemm_bf16<true>,  cudaFuncAttributeMaxDynamicSharedMemorySize, SMEM_TOT);

    const float scale = 0.08838834764831845f;   // 1/sqrt(128)
    dim3 blk(256);
    dim3 tblk(32, 8);

    // 0) split x; transpose+split weights
    split_arr<<<(TT * DD) / 1024, blk>>>(x, xh, xl);
    transpose_split<<<dim3(D3 / 32, DD / 32), tblk>>>(Wqkv, DD, D3, wqh, wql);
    transpose_split<<<dim3(DD / 32, DD / 32), tblk>>>(Wout, DD, DD, woh, wol);

    // 1) qkv = x @ W_qkv
    gemm_bf16<false><<<dim3(D3 / 128, TT / 128, 1), blk, SMEM_TOT>>>(
        xh, xl, DD, 0, wqh, wql, DD, 0, qkv, D3, 0, DD, 1.0f, nullptr, 0);

    // 2) l2norm + split q,k;  transpose + split v
    l2norm_split<<<(2 * TT * HH) / 8, blk>>>(qkv, qh, ql, kh, kl);
    vtrans_split<<<dim3(TT / 32, HDD / 32, HH), tblk>>>(qkv, vth, vtl);

    // 3) S_h = scale * Q_h @ K_h^T + mask
    gemm_bf16<true><<<dim3(TT / 128, TT / 128, HH), blk, SMEM_TOT>>>(
        qh, ql, HDD, (long)TT * HDD,
        kh, kl, HDD, (long)TT * HDD,
        S, TT, (long)TT * TT,
        HDD, scale, mask, TT);

    // 4) softmax rows -> split P written in place over S
    softmax_split_inplace<<<dim3(TT, HH), blk>>>(S);

    // 5) att_h = P_h @ V_h   (P hi/lo live inside S: row stride 2*TT bf16)
    gemm_bf16<false><<<dim3(1, TT / 128, HH), blk, SMEM_TOT>>>(
        (const bf16*)S, (const bf16*)S + TT, 2 * (long)TT, (long)TT * TT * 2,
        vth, vtl, TT, (long)HDD * TT,
        att, DD, HDD,
        TT, 1.0f, nullptr, 0);

    // 6) split att;  out = att @ W_out
    split_arr<<<(TT * DD) / 1024, blk>>>(att, ah, al);
    gemm_bf16<false><<<dim3(DD / 128, TT / 128, 1), blk, SMEM_TOT>>>(
        ah, al, DD, 0, woh, wol, DD, 0, out, DD, 0, DD, 1.0f, nullptr, 0);
}

// round 6
// speedup vs baseline: 2.5592x; 1.1656x over previous
#include <cuda_runtime.h>
#include <cuda_bf16.h>
#include <stdint.h>
#include <math.h>

// Problem constants
#define TT   4096
#define DD   2048
#define HH   16
#define HDD  128
#define D3   6144   // 3*D

typedef __nv_bfloat16 bf16;

// ---------------------------------------------------------------------------
// Scratch (__device__ globals -- allocation-free per harness rules). ~1.3 GB.
// ---------------------------------------------------------------------------
#define ALGN __align__(256)
__device__ ALGN bf16  g_xh [(size_t)TT*DD];
__device__ ALGN bf16  g_xl [(size_t)TT*DD];
__device__ ALGN bf16  g_wqh[(size_t)D3*DD];
__device__ ALGN bf16  g_wql[(size_t)D3*DD];
__device__ ALGN bf16  g_woh[(size_t)DD*DD];
__device__ ALGN bf16  g_wol[(size_t)DD*DD];
__device__ ALGN float g_qkv[(size_t)TT*D3];
__device__ ALGN bf16  g_qh [(size_t)HH*TT*HDD];
__device__ ALGN bf16  g_kh [(size_t)HH*TT*HDD];
__device__ ALGN bf16  g_vth[(size_t)HH*HDD*TT];
__device__ ALGN bf16  g_vtl[(size_t)HH*HDD*TT];
__device__ ALGN float g_S  [(size_t)HH*TT*TT];   // fp32 scores; softmax rewrites
                                                 // each row in place as bf16
                                                 // [hi x 4096 | lo x 4096]
__device__ ALGN float g_att[(size_t)TT*DD];
__device__ ALGN bf16  g_ah [(size_t)TT*DD];
__device__ ALGN bf16  g_al [(size_t)TT*DD];

// ---------------------------------------------------------------------------
// Helpers
// ---------------------------------------------------------------------------
__device__ __forceinline__ uint32_t smem_u32(const void* p) {
    uint32_t a;
    asm("{ .reg .u64 t; cvta.to.shared.u64 t, %1; cvt.u32.u64 %0, t; }" : "=r"(a) : "l"(p));
    return a;
}
__device__ __forceinline__ void split2(float v, bf16& h, bf16& l) {
    h = __float2bfloat16_rn(v);
    l = __float2bfloat16_rn(v - __bfloat162float(h));
}

#define LDSM4(r, addr) \
    asm volatile("ldmatrix.sync.aligned.m8n8.x4.shared.b16 {%0,%1,%2,%3}, [%4];" \
        : "=r"((r)[0]), "=r"((r)[1]), "=r"((r)[2]), "=r"((r)[3]) : "r"(addr))
#define MMA(acc, A, b0, b1) \
    asm volatile("mma.sync.aligned.m16n8k16.row.col.f32.bf16.bf16.f32 " \
        "{%0,%1,%2,%3}, {%4,%5,%6,%7}, {%8,%9}, {%0,%1,%2,%3};" \
        : "+f"((acc)[0]), "+f"((acc)[1]), "+f"((acc)[2]), "+f"((acc)[3]) \
        : "r"((A)[0]), "r"((A)[1]), "r"((A)[2]), "r"((A)[3]), \
          "r"(b0), "r"(b1))

__device__ __forceinline__ void cpa(uint32_t s, const bf16* g) {
    asm volatile("cp.async.cg.shared.global [%0], [%1], 16;" :: "r"(s), "l"(g));
}
#define CP_COMMIT asm volatile("cp.async.commit_group;" ::: "memory")
#define CP_WAIT0  asm volatile("cp.async.wait_group 0;"  ::: "memory")

// ---------------------------------------------------------------------------
// bf16(-split) HMMA GEMM: C[M,N] = alpha * (A @ B^T) (+ mask)
//   NT = 3: A,B given as hi/lo pairs; computes Ah.Bh + Ah.Bl + Al.Bh
//   NT = 1: plain bf16 (Al/Bl pointers ignored)
//   HEADX: head index packed into blockIdx.x (h = x & 15, n-tile = x >> 4)
//          so the 16 heads sharing one (m,n) mask tile are adjacent CTAs.
// Block tile 128x128, BK=32, 8 warps (2m x 4n; 64x32 per warp),
// cp.async 2-stage double buffer, ONE __syncthreads per K chunk.
// smem row stride 80 B (32 bf16 + 8 pad) -> conflict-free ldmatrix.
// ---------------------------------------------------------------------------
#define ROWB  80
#define TILB  10240       // one 128-row tile (128 * 80)

template <int NT>
__device__ __forceinline__ void stage_load(
    const bf16* __restrict__ Ah, const bf16* __restrict__ Al, long lda,
    const bf16* __restrict__ Bh, const bf16* __restrict__ Bl, long ldb,
    int bm, int bn, int k0, uint32_t sb, int tid)
{
    const uint32_t boff = (NT == 3 ? 2u : 1u) * TILB;
#pragma unroll
    for (int rep = 0; rep < 2; rep++) {
        int ci  = tid + rep * 256;
        int row = ci >> 2, c = ci & 3;
        uint32_t so = row * ROWB + c * 16;
        size_t ga = (size_t)(bm + row) * lda + k0 + c * 8;
        size_t gb = (size_t)(bn + row) * ldb + k0 + c * 8;
        cpa(sb + so,        Ah + ga);
        cpa(sb + boff + so, Bh + gb);
        if (NT == 3) {
            cpa(sb + TILB + so,        Al + ga);
            cpa(sb + boff + TILB + so, Bl + gb);
        }
    }
}

template <int NT, bool ADDMASK, bool HEADX>
__global__ __launch_bounds__(256)
void gemm_bf16(const bf16* __restrict__ Ah, const bf16* __restrict__ Al, long lda, long sA,
               const bf16* __restrict__ Bh, const bf16* __restrict__ Bl, long ldb, long sB,
               float* __restrict__ C, long ldc, long sC,
               int K, float alpha, const float* __restrict__ mask, long ldm)
{
    constexpr uint32_t STG  = (NT == 3 ? 4u : 2u) * TILB;
    constexpr uint32_t BOFF = (NT == 3 ? 2u : 1u) * TILB;

    extern __shared__ char smdyn[];
    const uint32_t sbase = smem_u32(smdyn);
    const int tid = threadIdx.x, lane = tid & 31, wid = tid >> 5;
    const int wm = wid >> 2, wn = wid & 3;          // 2 x 4 warp grid

    int h, bm, bn;
    if (HEADX) {
        h  = blockIdx.x & 15;
        bn = (blockIdx.x >> 4) * 128;
        bm = blockIdx.y * 128;
    } else {
        h  = blockIdx.z;
        bn = blockIdx.x * 128;
        bm = blockIdx.y * 128;
    }
    Ah += (size_t)h * sA;  Bh += (size_t)h * sB;
    if (NT == 3) { Al += (size_t)h * sA;  Bl += (size_t)h * sB; }
    C  += (size_t)h * sC;

    float acc[4][4][4];
#pragma unroll
    for (int i = 0; i < 4; i++)
#pragma unroll
        for (int j = 0; j < 4; j++)
#pragma unroll
            for (int r = 0; r < 4; r++) acc[i][j][r] = 0.0f;

    stage_load<NT>(Ah, Al, lda, Bh, Bl, ldb, bm, bn, 0, sbase, tid);
    CP_COMMIT;

    const int NC = K >> 5;
    for (int c = 0; c < NC; c++) {
        CP_WAIT0;            // stage c landed (only group in flight)
        __syncthreads();     // everyone sees stage c; done reading buf (c+1)&1
        if (c + 1 < NC) {
            stage_load<NT>(Ah, Al, lda, Bh, Bl, ldb, bm, bn, (c + 1) << 5,
                           sbase + ((c + 1) & 1) * STG, tid);
            CP_COMMIT;       // overlaps with compute below
        }

        const uint32_t ab = sbase + (c & 1) * STG;
#pragma unroll
        for (int ks = 0; ks < 2; ks++) {
            const int kb = ks * 32;   // 16 bf16 = 32 bytes
            uint32_t A_h[4][4], A_l[4][4], B_h[2][4], B_l[2][4];
#pragma unroll
            for (int mt = 0; mt < 4; mt++) {
                uint32_t ra = ab + (wm * 64 + mt * 16 + (lane & 15)) * ROWB
                                 + kb + (lane >> 4) * 16;
                LDSM4(A_h[mt], ra);
                if (NT == 3) LDSM4(A_l[mt], ra + TILB);
            }
#pragma unroll
            for (int np = 0; np < 2; np++) {
                // x4 loads fragments for two adjacent n8 tiles (n16 x k16)
                uint32_t rb = ab + BOFF
                                 + (wn * 32 + np * 16 + (lane & 7) + ((lane >> 4) << 3)) * ROWB
                                 + kb + ((lane >> 3) & 1) * 16;
                LDSM4(B_h[np], rb);
                if (NT == 3) LDSM4(B_l[np], rb + TILB);
            }
#pragma unroll
            for (int mt = 0; mt < 4; mt++)
#pragma unroll
                for (int nt = 0; nt < 4; nt++) {
                    const int np = nt >> 1, o = (nt & 1) * 2;
                    MMA(acc[mt][nt], A_h[mt], B_h[np][o], B_h[np][o + 1]);
                    if (NT == 3) {
                        MMA(acc[mt][nt], A_h[mt], B_l[np][o], B_l[np][o + 1]);
                        MMA(acc[mt][nt], A_l[mt], B_h[np][o], B_h[np][o + 1]);
                    }
                }
        }
        __syncthreads();
    }

    // Epilogue: c0,c1 at (r, c..c+1); c2,c3 at (r+8, c..c+1)
    const int rw = bm + wm * 64 + (lane >> 2);
    const int cw = bn + wn * 32 + (lane & 3) * 2;
#pragma unroll
    for (int mt = 0; mt < 4; mt++) {
#pragma unroll
        for (int nt = 0; nt < 4; nt++) {
            size_t r0 = rw + mt * 16;
            size_t c0 = cw + nt * 8;
            float2 v0 = make_float2(alpha * acc[mt][nt][0], alpha * acc[mt][nt][1]);
            float2 v1 = make_float2(alpha * acc[mt][nt][2], alpha * acc[mt][nt][3]);
            if (ADDMASK) {
                float2 m0 = *(const float2*)&mask[r0 * ldm + c0];
                float2 m1 = *(const float2*)&mask[(r0 + 8) * ldm + c0];
                v0.x += m0.x; v0.y += m0.y;
                v1.x += m1.x; v1.y += m1.y;
            }
            *(float2*)&C[r0 * ldc + c0] = v0;
            *(float2*)&C[(r0 + 8) * ldc + c0] = v1;
        }
    }
}

// ---------------------------------------------------------------------------
// Elementwise split: fp32 -> (hi, lo) bf16. One float4 per thread.
// ---------------------------------------------------------------------------
__global__ __launch_bounds__(256)
void split_arr(const float* __restrict__ src, bf16* __restrict__ oh, bf16* __restrict__ ol)
{
    size_t i = ((size_t)blockIdx.x * 256 + threadIdx.x) * 4;
    float4 v = *(const float4*)&src[i];
    bf16 h0, l0, h1, l1, h2, l2, h3, l3;
    split2(v.x, h0, l0); split2(v.y, h1, l1); split2(v.z, h2, l2); split2(v.w, h3, l3);
    __nv_bfloat162* ph = (__nv_bfloat162*)&oh[i];
    __nv_bfloat162* pl = (__nv_bfloat162*)&ol[i];
    ph[0] = __nv_bfloat162(h0, h1); ph[1] = __nv_bfloat162(h2, h3);
    pl[0] = __nv_bfloat162(l0, l1); pl[1] = __nv_bfloat162(l2, l3);
}

// ---------------------------------------------------------------------------
// Weight transpose + split: W[K,N] fp32 -> WT hi/lo [N,K] bf16
// ---------------------------------------------------------------------------
__global__ __launch_bounds__(256)
void transpose_split(const float* __restrict__ W, int K, int N,
                     bf16* __restrict__ Th, bf16* __restrict__ Tl)
{
    __shared__ float tile[32][33];
    const int n0 = blockIdx.x * 32, k0 = blockIdx.y * 32;
    const int tx = threadIdx.x, ty = threadIdx.y;   // 32 x 8
#pragma unroll
    for (int j = 0; j < 4; j++)
        tile[ty + j * 8][tx] = W[(size_t)(k0 + ty + j * 8) * N + n0 + tx];
    __syncthreads();
#pragma unroll
    for (int j = 0; j < 4; j++) {
        float v = tile[tx][ty + j * 8];
        bf16 h, l; split2(v, h, l);
        size_t o = (size_t)(n0 + ty + j * 8) * K + k0 + tx;
        Th[o] = h; Tl[o] = l;
    }
}

// ---------------------------------------------------------------------------
// L2-normalize q,k vectors (128 dims) -> bf16 (hi only; S GEMM is 1-term)
// per-head layout [H][T][128]. One warp per (part, t, h) vector.
// ---------------------------------------------------------------------------
__global__ __launch_bounds__(256)
void l2norm_bf16(const float* __restrict__ qkv,
                 bf16* __restrict__ qh, bf16* __restrict__ kh)
{
    int gw = (blockIdx.x * 256 + threadIdx.x) >> 5;
    int lane = threadIdx.x & 31;
    int part = gw / (TT * HH);
    int rem  = gw % (TT * HH);
    int t = rem / HH, h = rem % HH;
    const float* src = qkv + (size_t)t * D3 + part * DD + h * HDD;
    float4 v = *(const float4*)&src[lane * 4];
    float ss = v.x * v.x + v.y * v.y + v.z * v.z + v.w * v.w;
#pragma unroll
    for (int o = 16; o; o >>= 1) ss += __shfl_xor_sync(0xFFFFFFFFu, ss, o);
    float s = 1.0f / fmaxf(sqrtf(ss), 1e-12f);

    size_t o = ((size_t)h * TT + t) * HDD + lane * 4;
    bf16* dh = (part == 0 ? qh : kh) + o;
    ((__nv_bfloat162*)dh)[0] = __nv_bfloat162(__float2bfloat16_rn(v.x * s),
                                              __float2bfloat16_rn(v.y * s));
    ((__nv_bfloat162*)dh)[1] = __nv_bfloat162(__float2bfloat16_rn(v.z * s),
                                              __float2bfloat16_rn(v.w * s));
}

// ---------------------------------------------------------------------------
// V transpose + split: qkv[t][2D + h*128 + d] -> VT hi/lo [h][d][t]
// ---------------------------------------------------------------------------
__global__ __launch_bounds__(256)
void vtrans_split(const float* __restrict__ qkv,
                  bf16* __restrict__ vth, bf16* __restrict__ vtl)
{
    __shared__ float tile[32][33];
    const int h = blockIdx.z;
    const int t0 = blockIdx.x * 32, d0 = blockIdx.y * 32;
    const int tx = threadIdx.x, ty = threadIdx.y;   // 32 x 8
#pragma unroll
    for (int j = 0; j < 4; j++)
        tile[ty + j * 8][tx] = qkv[(size_t)(t0 + ty + j * 8) * D3 + 2 * DD + h * HDD + d0 + tx];
    __syncthreads();
#pragma unroll
    for (int j = 0; j < 4; j++) {
        float v = tile[tx][ty + j * 8];
        bf16 hh, ll; split2(v, hh, ll);
        size_t o = ((size_t)h * HDD + d0 + ty + j * 8) * TT + t0 + tx;
        vth[o] = hh; vtl[o] = ll;
    }
}

// ---------------------------------------------------------------------------
// Row softmax over S, IN PLACE: reads fp32 row (4096), writes the same 16KB
// as [4096 x bf16 hi | 4096 x bf16 lo]. One block (256 threads) per (h, row).
// ---------------------------------------------------------------------------
__global__ __launch_bounds__(256)
void softmax_split_inplace(float* __restrict__ S)
{
    size_t base = ((size_t)blockIdx.y * TT + blockIdx.x) * TT;
    float* row = S + base;
    const int tid = threadIdx.x;
    __shared__ float red[8];

    float4 v[4];
    float m = -INFINITY;
#pragma unroll
    for (int r = 0; r < 4; r++) {
        v[r] = *(const float4*)&row[tid * 4 + r * 1024];
        m = fmaxf(m, fmaxf(fmaxf(v[r].x, v[r].y), fmaxf(v[r].z, v[r].w)));
    }
#pragma unroll
    for (int o = 16; o; o >>= 1) m = fmaxf(m, __shfl_xor_sync(0xFFFFFFFFu, m, o));
    if ((tid & 31) == 0) red[tid >> 5] = m;
    __syncthreads();
    if (tid < 32) {
        float t = (tid < 8) ? red[tid] : -INFINITY;
#pragma unroll
        for (int o = 4; o; o >>= 1) t = fmaxf(t, __shfl_xor_sync(0xFFFFFFFFu, t, o));
        if (tid == 0) red[0] = t;
    }
    __syncthreads();
    m = red[0];
    __syncthreads();

    float s = 0.0f;
#pragma unroll
    for (int r = 0; r < 4; r++) {
        v[r].x = __expf(v[r].x - m); v[r].y = __expf(v[r].y - m);
        v[r].z = __expf(v[r].z - m); v[r].w = __expf(v[r].w - m);
        s += v[r].x + v[r].y + v[r].z + v[r].w;
    }
#pragma unroll
    for (int o = 16; o; o >>= 1) s += __shfl_xor_sync(0xFFFFFFFFu, s, o);
    if ((tid & 31) == 0) red[tid >> 5] = s;
    __syncthreads();
    if (tid < 32) {
        float t = (tid < 8) ? red[tid] : 0.0f;
#pragma unroll
        for (int o = 4; o; o >>= 1) t += __shfl_xor_sync(0xFFFFFFFFu, t, o);
        if (tid == 0) red[0] = t;
    }
    __syncthreads();
    float inv = 1.0f / red[0];

    __syncthreads();
    bf16* Ph = (bf16*)row;            // elements 0..4095
    bf16* Pl = (bf16*)row + TT;       // elements 4096..8191
#pragma unroll
    for (int r = 0; r < 4; r++) {
        int o = tid * 4 + r * 1024;
        bf16 h0, l0, h1, l1, h2, l2, h3, l3;
        split2(v[r].x * inv, h0, l0); split2(v[r].y * inv, h1, l1);
        split2(v[r].z * inv, h2, l2); split2(v[r].w * inv, h3, l3);
        ((__nv_bfloat162*)&Ph[o])[0] = __nv_bfloat162(h0, h1);
        ((__nv_bfloat162*)&Ph[o])[1] = __nv_bfloat162(h2, h3);
        ((__nv_bfloat162*)&Pl[o])[0] = __nv_bfloat162(l0, l1);
        ((__nv_bfloat162*)&Pl[o])[1] = __nv_bfloat162(l2, l3);
    }
}

// ---------------------------------------------------------------------------
// Launch
// ---------------------------------------------------------------------------
extern "C" void kernel_launch(void* const* d_in, const int* in_sizes, int n_in,
                              void* d_out, int out_size)
{
    const float* x    = (const float*)d_in[0];   // [T, D]
    const float* mask = (const float*)d_in[1];   // [T, T]
    const float* Wqkv = (const float*)d_in[2];   // [D, 3D]
    const float* Wout = (const float*)d_in[3];   // [D, D]
    float* out = (float*)d_out;                  // [T, D]

    float *qkv, *S, *att;
    bf16 *xh, *xl, *wqh, *wql, *woh, *wol, *qh, *kh, *vth, *vtl, *ah, *al;
    cudaGetSymbolAddress((void**)&qkv, g_qkv);
    cudaGetSymbolAddress((void**)&S,   g_S);
    cudaGetSymbolAddress((void**)&att, g_att);
    cudaGetSymbolAddress((void**)&xh,  g_xh);   cudaGetSymbolAddress((void**)&xl,  g_xl);
    cudaGetSymbolAddress((void**)&wqh, g_wqh);  cudaGetSymbolAddress((void**)&wql, g_wql);
    cudaGetSymbolAddress((void**)&woh, g_woh);  cudaGetSymbolAddress((void**)&wol, g_wol);
    cudaGetSymbolAddress((void**)&qh,  g_qh);   cudaGetSymbolAddress((void**)&kh,  g_kh);
    cudaGetSymbolAddress((void**)&vth, g_vth);  cudaGetSymbolAddress((void**)&vtl, g_vtl);
    cudaGetSymbolAddress((void**)&ah,  g_ah);   cudaGetSymbolAddress((void**)&al,  g_al);

    const int SM3 = 2 * 4 * TILB;   // 81920 B (3-term)
    const int SM1 = 2 * 2 * TILB;   // 40960 B (1-term)
    cudaFuncSetAttribute(gemm_bf16<3, false, false>, cudaFuncAttributeMaxDynamicSharedMemorySize, SM3);
    cudaFuncSetAttribute(gemm_bf16<1, true,  true >, cudaFuncAttributeMaxDynamicSharedMemorySize, SM1);

    const float scale = 0.08838834764831845f;   // 1/sqrt(128)
    dim3 blk(256);
    dim3 tblk(32, 8);

    // 0) split x; transpose+split weights
    split_arr<<<(TT * DD) / 1024, blk>>>(x, xh, xl);
    transpose_split<<<dim3(D3 / 32, DD / 32), tblk>>>(Wqkv, DD, D3, wqh, wql);
    transpose_split<<<dim3(DD / 32, DD / 32), tblk>>>(Wout, DD, DD, woh, wol);

    // 1) qkv = x @ W_qkv   (3-term split)
    gemm_bf16<3, false, false><<<dim3(D3 / 128, TT / 128, 1), blk, SM3>>>(
        xh, xl, DD, 0, wqh, wql, DD, 0, qkv, D3, 0, DD, 1.0f, nullptr, 0);

    // 2) l2norm q,k (bf16, 1-term suffices);  transpose + split v
    l2norm_bf16<<<(2 * TT * HH) / 8, blk>>>(qkv, qh, kh);
    vtrans_split<<<dim3(TT / 32, HDD / 32, HH), tblk>>>(qkv, vth, vtl);

    // 3) S_h = scale * Q_h @ K_h^T + mask   (1-term bf16; heads adjacent in x
    //    so the shared mask tile stays L2-resident)
    gemm_bf16<1, true, true><<<dim3(HH * (TT / 128), TT / 128, 1), blk, SM1>>>(
        qh, nullptr, HDD, (long)TT * HDD,
        kh, nullptr, HDD, (long)TT * HDD,
        S, TT, (long)TT * TT,
        HDD, scale, mask, TT);

    // 4) softmax rows -> split P written in place over S
    softmax_split_inplace<<<dim3(TT, HH), blk>>>(S);

    // 5) att_h = P_h @ V_h   (3-term; P hi/lo live inside S, row stride 2*TT bf16)
    gemm_bf16<3, false, false><<<dim3(1, TT / 128, HH), blk, SM3>>>(
        (const bf16*)S, (const bf16*)S + TT, 2 * (long)TT, (long)TT * TT * 2,
        vth, vtl, TT, (long)HDD * TT,
        att, DD, HDD,
        TT, 1.0f, nullptr, 0);

    // 6) split att;  out = att @ W_out   (3-term)
    split_arr<<<(TT * DD) / 1024, blk>>>(att, ah, al);
    gemm_bf16<3, false, false><<<dim3(DD / 128, TT / 128, 1), blk, SM3>>>(
        ah, al, DD, 0, woh, wol, DD, 0, out, DD, 0, DD, 1.0f, nullptr, 0);
}

// round 7
// speedup vs baseline: 2.9069x; 1.1359x over previous
#include <cuda_runtime.h>
#include <cuda_bf16.h>
#include <stdint.h>
#include <math.h>

// Problem constants
#define TT   4096
#define DD   2048
#define HH   16
#define HDD  128
#define D3   6144   // 3*D

typedef __nv_bfloat16 bf16;

// ---------------------------------------------------------------------------
// Scratch (__device__ globals -- allocation-free per harness rules). ~1.3 GB.
// ---------------------------------------------------------------------------
#define ALGN __align__(256)
__device__ ALGN bf16  g_xh [(size_t)TT*DD];
__device__ ALGN bf16  g_xl [(size_t)TT*DD];
__device__ ALGN bf16  g_wqh[(size_t)D3*DD];
__device__ ALGN bf16  g_wql[(size_t)D3*DD];
__device__ ALGN bf16  g_woh[(size_t)DD*DD];
__device__ ALGN bf16  g_wol[(size_t)DD*DD];
__device__ ALGN float g_qkv[(size_t)TT*D3];
__device__ ALGN bf16  g_qh [(size_t)HH*TT*HDD];
__device__ ALGN bf16  g_kh [(size_t)HH*TT*HDD];
__device__ ALGN bf16  g_vth[(size_t)HH*HDD*TT];
__device__ ALGN bf16  g_vtl[(size_t)HH*HDD*TT];
__device__ ALGN float g_S  [(size_t)HH*TT*TT];   // fp32 scores; softmax rewrites
                                                 // each row in place as bf16
                                                 // [hi x 4096 | lo x 4096]
__device__ ALGN bf16  g_ah [(size_t)TT*DD];      // attention out hi/lo (written
__device__ ALGN bf16  g_al [(size_t)TT*DD];      // directly by PV epilogue)

// ---------------------------------------------------------------------------
// Helpers
// ---------------------------------------------------------------------------
__device__ __forceinline__ uint32_t smem_u32(const void* p) {
    uint32_t a;
    asm("{ .reg .u64 t; cvta.to.shared.u64 t, %1; cvt.u32.u64 %0, t; }" : "=r"(a) : "l"(p));
    return a;
}
__device__ __forceinline__ void split2(float v, bf16& h, bf16& l) {
    h = __float2bfloat16_rn(v);
    l = __float2bfloat16_rn(v - __bfloat162float(h));
}

#define LDSM4(r, addr) \
    asm volatile("ldmatrix.sync.aligned.m8n8.x4.shared.b16 {%0,%1,%2,%3}, [%4];" \
        : "=r"((r)[0]), "=r"((r)[1]), "=r"((r)[2]), "=r"((r)[3]) : "r"(addr))
#define MMA(acc, A, b0, b1) \
    asm volatile("mma.sync.aligned.m16n8k16.row.col.f32.bf16.bf16.f32 " \
        "{%0,%1,%2,%3}, {%4,%5,%6,%7}, {%8,%9}, {%0,%1,%2,%3};" \
        : "+f"((acc)[0]), "+f"((acc)[1]), "+f"((acc)[2]), "+f"((acc)[3]) \
        : "r"((A)[0]), "r"((A)[1]), "r"((A)[2]), "r"((A)[3]), \
          "r"(b0), "r"(b1))

__device__ __forceinline__ void cpa(uint32_t s, const bf16* g) {
    asm volatile("cp.async.cg.shared.global [%0], [%1], 16;" :: "r"(s), "l"(g));
}
#define CP_COMMIT asm volatile("cp.async.commit_group;" ::: "memory")
#define CP_WAIT0  asm volatile("cp.async.wait_group 0;"  ::: "memory")

// ---------------------------------------------------------------------------
// bf16(-split) HMMA GEMM: C[M,N] = alpha * (A @ B^T) (+ mask)
//   NT = 3: A,B given as hi/lo pairs; computes Ah.Bh + Ah.Bl + Al.Bh
//           (term-major issue order: 16 independent accumulators between
//            consecutive MMAs on the same accumulator)
//   NT = 1: plain bf16 (Al/Bl pointers ignored)
//   HEADX:  head index packed into blockIdx.x (h = x & 15, n-tile = x >> 4)
//   OUTM:   0 -> fp32 C;  1 -> write split bf16 directly to Chi/Clo
// Block tile 128x128, BK=32, 8 warps (2m x 4n; 64x32 per warp),
// cp.async 2-stage double buffer, one __syncthreads per K chunk.
// ---------------------------------------------------------------------------
#define ROWB  80
#define TILB  10240       // one 128-row tile (128 * 80)

template <int NT>
__device__ __forceinline__ void stage_load(
    const bf16* __restrict__ Ah, const bf16* __restrict__ Al, long lda,
    const bf16* __restrict__ Bh, const bf16* __restrict__ Bl, long ldb,
    int bm, int bn, int k0, uint32_t sb, int tid)
{
    const uint32_t boff = (NT == 3 ? 2u : 1u) * TILB;
#pragma unroll
    for (int rep = 0; rep < 2; rep++) {
        int ci  = tid + rep * 256;
        int row = ci >> 2, c = ci & 3;
        uint32_t so = row * ROWB + c * 16;
        size_t ga = (size_t)(bm + row) * lda + k0 + c * 8;
        size_t gb = (size_t)(bn + row) * ldb + k0 + c * 8;
        cpa(sb + so,        Ah + ga);
        cpa(sb + boff + so, Bh + gb);
        if (NT == 3) {
            cpa(sb + TILB + so,        Al + ga);
            cpa(sb + boff + TILB + so, Bl + gb);
        }
    }
}

template <int NT, bool ADDMASK, bool HEADX, int OUTM>
__global__ __launch_bounds__(256)
void gemm_bf16(const bf16* __restrict__ Ah, const bf16* __restrict__ Al, long lda, long sA,
               const bf16* __restrict__ Bh, const bf16* __restrict__ Bl, long ldb, long sB,
               float* __restrict__ C, bf16* __restrict__ Chi, bf16* __restrict__ Clo,
               long ldc, long sC,
               int K, float alpha, const float* __restrict__ mask, long ldm)
{
    constexpr uint32_t STG  = (NT == 3 ? 4u : 2u) * TILB;
    constexpr uint32_t BOFF = (NT == 3 ? 2u : 1u) * TILB;

    extern __shared__ char smdyn[];
    const uint32_t sbase = smem_u32(smdyn);
    const int tid = threadIdx.x, lane = tid & 31, wid = tid >> 5;
    const int wm = wid >> 2, wn = wid & 3;          // 2 x 4 warp grid

    int h, bm, bn;
    if (HEADX) {
        h  = blockIdx.x & 15;
        bn = (blockIdx.x >> 4) * 128;
        bm = blockIdx.y * 128;
    } else {
        h  = blockIdx.z;
        bn = blockIdx.x * 128;
        bm = blockIdx.y * 128;
    }
    Ah += (size_t)h * sA;  Bh += (size_t)h * sB;
    if (NT == 3) { Al += (size_t)h * sA;  Bl += (size_t)h * sB; }
    if (OUTM == 0) C += (size_t)h * sC;
    else { Chi += (size_t)h * sC; Clo += (size_t)h * sC; }

    float acc[4][4][4];
#pragma unroll
    for (int i = 0; i < 4; i++)
#pragma unroll
        for (int j = 0; j < 4; j++)
#pragma unroll
            for (int r = 0; r < 4; r++) acc[i][j][r] = 0.0f;

    stage_load<NT>(Ah, Al, lda, Bh, Bl, ldb, bm, bn, 0, sbase, tid);
    CP_COMMIT;

    const int NC = K >> 5;
    for (int c = 0; c < NC; c++) {
        CP_WAIT0;
        __syncthreads();
        if (c + 1 < NC) {
            stage_load<NT>(Ah, Al, lda, Bh, Bl, ldb, bm, bn, (c + 1) << 5,
                           sbase + ((c + 1) & 1) * STG, tid);
            CP_COMMIT;       // overlaps with compute below
        }

        const uint32_t ab = sbase + (c & 1) * STG;
#pragma unroll
        for (int ks = 0; ks < 2; ks++) {
            const int kb = ks * 32;   // 16 bf16 = 32 bytes
            uint32_t A_h[4][4], A_l[4][4], B_h[2][4], B_l[2][4];
#pragma unroll
            for (int mt = 0; mt < 4; mt++) {
                uint32_t ra = ab + (wm * 64 + mt * 16 + (lane & 15)) * ROWB
                                 + kb + (lane >> 4) * 16;
                LDSM4(A_h[mt], ra);
                if (NT == 3) LDSM4(A_l[mt], ra + TILB);
            }
#pragma unroll
            for (int np = 0; np < 2; np++) {
                uint32_t rb = ab + BOFF
                                 + (wn * 32 + np * 16 + (lane & 7) + ((lane >> 4) << 3)) * ROWB
                                 + kb + ((lane >> 3) & 1) * 16;
                LDSM4(B_h[np], rb);
                if (NT == 3) LDSM4(B_l[np], rb + TILB);
            }
            // term-major: consecutive MMAs always hit different accumulators
#pragma unroll
            for (int t = 0; t < NT; t++) {
                const uint32_t (*Af)[4] = (t == 2) ? A_l : A_h;
                const uint32_t (*Bf)[4] = (t == 1) ? B_l : B_h;
#pragma unroll
                for (int mt = 0; mt < 4; mt++)
#pragma unroll
                    for (int nt = 0; nt < 4; nt++) {
                        const int np = nt >> 1, o = (nt & 1) * 2;
                        MMA(acc[mt][nt], Af[mt], Bf[np][o], Bf[np][o + 1]);
                    }
            }
        }
        __syncthreads();
    }

    // Epilogue: c0,c1 at (r, c..c+1); c2,c3 at (r+8, c..c+1)
    const int rw = bm + wm * 64 + (lane >> 2);
    const int cw = bn + wn * 32 + (lane & 3) * 2;
#pragma unroll
    for (int mt = 0; mt < 4; mt++) {
#pragma unroll
        for (int nt = 0; nt < 4; nt++) {
            size_t r0 = rw + mt * 16;
            size_t c0 = cw + nt * 8;
            float2 v0 = make_float2(alpha * acc[mt][nt][0], alpha * acc[mt][nt][1]);
            float2 v1 = make_float2(alpha * acc[mt][nt][2], alpha * acc[mt][nt][3]);
            if (ADDMASK) {
                float2 m0 = *(const float2*)&mask[r0 * ldm + c0];
                float2 m1 = *(const float2*)&mask[(r0 + 8) * ldm + c0];
                v0.x += m0.x; v0.y += m0.y;
                v1.x += m1.x; v1.y += m1.y;
            }
            if (OUTM == 0) {
                *(float2*)&C[r0 * ldc + c0] = v0;
                *(float2*)&C[(r0 + 8) * ldc + c0] = v1;
            } else {
                bf16 h0, l0, h1, l1;
                split2(v0.x, h0, l0); split2(v0.y, h1, l1);
                *(__nv_bfloat162*)&Chi[r0 * ldc + c0] = __nv_bfloat162(h0, h1);
                *(__nv_bfloat162*)&Clo[r0 * ldc + c0] = __nv_bfloat162(l0, l1);
                split2(v1.x, h0, l0); split2(v1.y, h1, l1);
                *(__nv_bfloat162*)&Chi[(r0 + 8) * ldc + c0] = __nv_bfloat162(h0, h1);
                *(__nv_bfloat162*)&Clo[(r0 + 8) * ldc + c0] = __nv_bfloat162(l0, l1);
            }
        }
    }
}

// ---------------------------------------------------------------------------
// Elementwise split: fp32 -> (hi, lo) bf16. One float4 per thread.
// ---------------------------------------------------------------------------
__global__ __launch_bounds__(256)
void split_arr(const float* __restrict__ src, bf16* __restrict__ oh, bf16* __restrict__ ol)
{
    size_t i = ((size_t)blockIdx.x * 256 + threadIdx.x) * 4;
    float4 v = *(const float4*)&src[i];
    bf16 h0, l0, h1, l1, h2, l2, h3, l3;
    split2(v.x, h0, l0); split2(v.y, h1, l1); split2(v.z, h2, l2); split2(v.w, h3, l3);
    __nv_bfloat162* ph = (__nv_bfloat162*)&oh[i];
    __nv_bfloat162* pl = (__nv_bfloat162*)&ol[i];
    ph[0] = __nv_bfloat162(h0, h1); ph[1] = __nv_bfloat162(h2, h3);
    pl[0] = __nv_bfloat162(l0, l1); pl[1] = __nv_bfloat162(l2, l3);
}

// ---------------------------------------------------------------------------
// Weight transpose + split: W[K,N] fp32 -> WT hi/lo [N,K] bf16
// ---------------------------------------------------------------------------
__global__ __launch_bounds__(256)
void transpose_split(const float* __restrict__ W, int K, int N,
                     bf16* __restrict__ Th, bf16* __restrict__ Tl)
{
    __shared__ float tile[32][33];
    const int n0 = blockIdx.x * 32, k0 = blockIdx.y * 32;
    const int tx = threadIdx.x, ty = threadIdx.y;   // 32 x 8
#pragma unroll
    for (int j = 0; j < 4; j++)
        tile[ty + j * 8][tx] = W[(size_t)(k0 + ty + j * 8) * N + n0 + tx];
    __syncthreads();
#pragma unroll
    for (int j = 0; j < 4; j++) {
        float v = tile[tx][ty + j * 8];
        bf16 h, l; split2(v, h, l);
        size_t o = (size_t)(n0 + ty + j * 8) * K + k0 + tx;
        Th[o] = h; Tl[o] = l;
    }
}

// ---------------------------------------------------------------------------
// L2-normalize q,k vectors (128 dims) -> bf16, per-head layout [H][T][128].
// One warp per (part, t, h) vector.
// ---------------------------------------------------------------------------
__global__ __launch_bounds__(256)
void l2norm_bf16(const float* __restrict__ qkv,
                 bf16* __restrict__ qh, bf16* __restrict__ kh)
{
    int gw = (blockIdx.x * 256 + threadIdx.x) >> 5;
    int lane = threadIdx.x & 31;
    int part = gw / (TT * HH);
    int rem  = gw % (TT * HH);
    int t = rem / HH, h = rem % HH;
    const float* src = qkv + (size_t)t * D3 + part * DD + h * HDD;
    float4 v = *(const float4*)&src[lane * 4];
    float ss = v.x * v.x + v.y * v.y + v.z * v.z + v.w * v.w;
#pragma unroll
    for (int o = 16; o; o >>= 1) ss += __shfl_xor_sync(0xFFFFFFFFu, ss, o);
    float s = 1.0f / fmaxf(sqrtf(ss), 1e-12f);

    size_t o = ((size_t)h * TT + t) * HDD + lane * 4;
    bf16* dh = (part == 0 ? qh : kh) + o;
    ((__nv_bfloat162*)dh)[0] = __nv_bfloat162(__float2bfloat16_rn(v.x * s),
                                              __float2bfloat16_rn(v.y * s));
    ((__nv_bfloat162*)dh)[1] = __nv_bfloat162(__float2bfloat16_rn(v.z * s),
                                              __float2bfloat16_rn(v.w * s));
}

// ---------------------------------------------------------------------------
// V transpose + split: qkv[t][2D + h*128 + d] -> VT hi/lo [h][d][t]
// ---------------------------------------------------------------------------
__global__ __launch_bounds__(256)
void vtrans_split(const float* __restrict__ qkv,
                  bf16* __restrict__ vth, bf16* __restrict__ vtl)
{
    __shared__ float tile[32][33];
    const int h = blockIdx.z;
    const int t0 = blockIdx.x * 32, d0 = blockIdx.y * 32;
    const int tx = threadIdx.x, ty = threadIdx.y;   // 32 x 8
#pragma unroll
    for (int j = 0; j < 4; j++)
        tile[ty + j * 8][tx] = qkv[(size_t)(t0 + ty + j * 8) * D3 + 2 * DD + h * HDD + d0 + tx];
    __syncthreads();
#pragma unroll
    for (int j = 0; j < 4; j++) {
        float v = tile[tx][ty + j * 8];
        bf16 hh, ll; split2(v, hh, ll);
        size_t o = ((size_t)h * HDD + d0 + ty + j * 8) * TT + t0 + tx;
        vth[o] = hh; vtl[o] = ll;
    }
}

// ---------------------------------------------------------------------------
// Row softmax over S, IN PLACE: reads fp32 row (4096), writes the same 16KB
// as [4096 x bf16 hi | 4096 x bf16 lo]. One block (256 threads) per (h, row).
// ---------------------------------------------------------------------------
__global__ __launch_bounds__(256)
void softmax_split_inplace(float* __restrict__ S)
{
    size_t base = ((size_t)blockIdx.y * TT + blockIdx.x) * TT;
    float* row = S + base;
    const int tid = threadIdx.x;
    __shared__ float red[8];

    float4 v[4];
    float m = -INFINITY;
#pragma unroll
    for (int r = 0; r < 4; r++) {
        v[r] = *(const float4*)&row[tid * 4 + r * 1024];
        m = fmaxf(m, fmaxf(fmaxf(v[r].x, v[r].y), fmaxf(v[r].z, v[r].w)));
    }
#pragma unroll
    for (int o = 16; o; o >>= 1) m = fmaxf(m, __shfl_xor_sync(0xFFFFFFFFu, m, o));
    if ((tid & 31) == 0) red[tid >> 5] = m;
    __syncthreads();
    if (tid < 32) {
        float t = (tid < 8) ? red[tid] : -INFINITY;
#pragma unroll
        for (int o = 4; o; o >>= 1) t = fmaxf(t, __shfl_xor_sync(0xFFFFFFFFu, t, o));
        if (tid == 0) red[0] = t;
    }
    __syncthreads();
    m = red[0];
    __syncthreads();

    float s = 0.0f;
#pragma unroll
    for (int r = 0; r < 4; r++) {
        v[r].x = __expf(v[r].x - m); v[r].y = __expf(v[r].y - m);
        v[r].z = __expf(v[r].z - m); v[r].w = __expf(v[r].w - m);
        s += v[r].x + v[r].y + v[r].z + v[r].w;
    }
#pragma unroll
    for (int o = 16; o; o >>= 1) s += __shfl_xor_sync(0xFFFFFFFFu, s, o);
    if ((tid & 31) == 0) red[tid >> 5] = s;
    __syncthreads();
    if (tid < 32) {
        float t = (tid < 8) ? red[tid] : 0.0f;
#pragma unroll
        for (int o = 4; o; o >>= 1) t += __shfl_xor_sync(0xFFFFFFFFu, t, o);
        if (tid == 0) red[0] = t;
    }
    __syncthreads();
    float inv = 1.0f / red[0];

    __syncthreads();
    bf16* Ph = (bf16*)row;            // elements 0..4095
    bf16* Pl = (bf16*)row + TT;       // elements 4096..8191
#pragma unroll
    for (int r = 0; r < 4; r++) {
        int o = tid * 4 + r * 1024;
        bf16 h0, l0, h1, l1, h2, l2, h3, l3;
        split2(v[r].x * inv, h0, l0); split2(v[r].y * inv, h1, l1);
        split2(v[r].z * inv, h2, l2); split2(v[r].w * inv, h3, l3);
        ((__nv_bfloat162*)&Ph[o])[0] = __nv_bfloat162(h0, h1);
        ((__nv_bfloat162*)&Ph[o])[1] = __nv_bfloat162(h2, h3);
        ((__nv_bfloat162*)&Pl[o])[0] = __nv_bfloat162(l0, l1);
        ((__nv_bfloat162*)&Pl[o])[1] = __nv_bfloat162(l2, l3);
    }
}

// ---------------------------------------------------------------------------
// Launch
// ---------------------------------------------------------------------------
extern "C" void kernel_launch(void* const* d_in, const int* in_sizes, int n_in,
                              void* d_out, int out_size)
{
    const float* x    = (const float*)d_in[0];   // [T, D]
    const float* mask = (const float*)d_in[1];   // [T, T]
    const float* Wqkv = (const float*)d_in[2];   // [D, 3D]
    const float* Wout = (const float*)d_in[3];   // [D, D]
    float* out = (float*)d_out;                  // [T, D]

    float *qkv, *S;
    bf16 *xh, *xl, *wqh, *wql, *woh, *wol, *qh, *kh, *vth, *vtl, *ah, *al;
    cudaGetSymbolAddress((void**)&qkv, g_qkv);
    cudaGetSymbolAddress((void**)&S,   g_S);
    cudaGetSymbolAddress((void**)&xh,  g_xh);   cudaGetSymbolAddress((void**)&xl,  g_xl);
    cudaGetSymbolAddress((void**)&wqh, g_wqh);  cudaGetSymbolAddress((void**)&wql, g_wql);
    cudaGetSymbolAddress((void**)&woh, g_woh);  cudaGetSymbolAddress((void**)&wol, g_wol);
    cudaGetSymbolAddress((void**)&qh,  g_qh);   cudaGetSymbolAddress((void**)&kh,  g_kh);
    cudaGetSymbolAddress((void**)&vth, g_vth);  cudaGetSymbolAddress((void**)&vtl, g_vtl);
    cudaGetSymbolAddress((void**)&ah,  g_ah);   cudaGetSymbolAddress((void**)&al,  g_al);

    const int SM3 = 2 * 4 * TILB;   // 81920 B (3-term)
    const int SM1 = 2 * 2 * TILB;   // 40960 B (1-term)
    cudaFuncSetAttribute(gemm_bf16<3, false, false, 0>, cudaFuncAttributeMaxDynamicSharedMemorySize, SM3);
    cudaFuncSetAttribute(gemm_bf16<3, false, false, 1>, cudaFuncAttributeMaxDynamicSharedMemorySize, SM3);
    cudaFuncSetAttribute(gemm_bf16<1, false, false, 0>, cudaFuncAttributeMaxDynamicSharedMemorySize, SM1);
    cudaFuncSetAttribute(gemm_bf16<1, true,  true,  0>, cudaFuncAttributeMaxDynamicSharedMemorySize, SM1);

    const float scale = 0.08838834764831845f;   // 1/sqrt(128)
    dim3 blk(256);
    dim3 tblk(32, 8);

    // 0) split x; transpose+split weights
    split_arr<<<(TT * DD) / 1024, blk>>>(x, xh, xl);
    transpose_split<<<dim3(D3 / 32, DD / 32), tblk>>>(Wqkv, DD, D3, wqh, wql);
    transpose_split<<<dim3(DD / 32, DD / 32), tblk>>>(Wout, DD, DD, woh, wol);

    // 1a) qk part of qkv (cols 0..4095): 1-term bf16 (l2norm absorbs the error)
    gemm_bf16<1, false, false, 0><<<dim3(2 * DD / 128, TT / 128, 1), blk, SM1>>>(
        xh, nullptr, DD, 0, wqh, nullptr, DD, 0,
        qkv, nullptr, nullptr, D3, 0, DD, 1.0f, nullptr, 0);
    // 1b) v part of qkv (cols 4096..6143): 3-term split
    gemm_bf16<3, false, false, 0><<<dim3(DD / 128, TT / 128, 1), blk, SM3>>>(
        xh, xl, DD, 0, wqh + (size_t)2 * DD * DD, wql + (size_t)2 * DD * DD, DD, 0,
        qkv + 2 * DD, nullptr, nullptr, D3, 0, DD, 1.0f, nullptr, 0);

    // 2) l2norm q,k (bf16);  transpose + split v
    l2norm_bf16<<<(2 * TT * HH) / 8, blk>>>(qkv, qh, kh);
    vtrans_split<<<dim3(TT / 32, HDD / 32, HH), tblk>>>(qkv, vth, vtl);

    // 3) S_h = scale * Q_h @ K_h^T + mask   (1-term bf16; heads adjacent in x
    //    so the shared mask tile stays L2-resident)
    gemm_bf16<1, true, true, 0><<<dim3(HH * (TT / 128), TT / 128, 1), blk, SM1>>>(
        qh, nullptr, HDD, (long)TT * HDD,
        kh, nullptr, HDD, (long)TT * HDD,
        S, nullptr, nullptr, TT, (long)TT * TT,
        HDD, scale, mask, TT);

    // 4) softmax rows -> split P written in place over S
    softmax_split_inplace<<<dim3(TT, HH), blk>>>(S);

    // 5) att_h = P_h @ V_h (3-term), epilogue writes split bf16 ah/al directly
    gemm_bf16<3, false, false, 1><<<dim3(1, TT / 128, HH), blk, SM3>>>(
        (const bf16*)S, (const bf16*)S + TT, 2 * (long)TT, (long)TT * TT * 2,
        vth, vtl, TT, (long)HDD * TT,
        nullptr, ah, al, DD, HDD,
        TT, 1.0f, nullptr, 0);

    // 6) out = att @ W_out   (3-term)
    gemm_bf16<3, false, false, 0><<<dim3(DD / 128, TT / 128, 1), blk, SM3>>>(
        ah, al, DD, 0, woh, wol, DD, 0,
        out, nullptr, nullptr, DD, 0, DD, 1.0f, nullptr, 0);
}

// round 10
// speedup vs baseline: 3.4704x; 1.1938x over previous
#include <cuda_runtime.h>
#include <cuda_bf16.h>
#include <stdint.h>
#include <math.h>

// Problem constants
#define TT   4096
#define DD   2048
#define HH   16
#define HDD  128
#define D3   6144   // 3*D

typedef __nv_bfloat16 bf16;

// ---------------------------------------------------------------------------
// Scratch (__device__ globals -- allocation-free per harness rules).
// ---------------------------------------------------------------------------
#define ALGN __align__(256)
__device__ ALGN bf16  g_xh [(size_t)TT*DD];
__device__ ALGN bf16  g_xl [(size_t)TT*DD];
__device__ ALGN bf16  g_wqh[(size_t)D3*DD];
__device__ ALGN bf16  g_wql[(size_t)D3*DD];
__device__ ALGN bf16  g_woh[(size_t)DD*DD];
__device__ ALGN bf16  g_wol[(size_t)DD*DD];
__device__ ALGN float g_qkv[(size_t)TT*D3];
__device__ ALGN bf16  g_qh [(size_t)HH*TT*HDD];
__device__ ALGN bf16  g_kh [(size_t)HH*TT*HDD];
__device__ ALGN bf16  g_vth[(size_t)HH*HDD*TT];
__device__ ALGN bf16  g_vtl[(size_t)HH*HDD*TT];
__device__ ALGN bf16  g_ah [(size_t)TT*DD];      // attention out hi/lo (written
__device__ ALGN bf16  g_al [(size_t)TT*DD];      // directly by flash epilogue)

// ---------------------------------------------------------------------------
// Helpers
// ---------------------------------------------------------------------------
__device__ __forceinline__ uint32_t smem_u32(const void* p) {
    uint32_t a;
    asm("{ .reg .u64 t; cvta.to.shared.u64 t, %1; cvt.u32.u64 %0, t; }" : "=r"(a) : "l"(p));
    return a;
}
__device__ __forceinline__ void split2(float v, bf16& h, bf16& l) {
    h = __float2bfloat16_rn(v);
    l = __float2bfloat16_rn(v - __bfloat162float(h));
}

#define LDSM4(r, addr) \
    asm volatile("ldmatrix.sync.aligned.m8n8.x4.shared.b16 {%0,%1,%2,%3}, [%4];" \
        : "=r"((r)[0]), "=r"((r)[1]), "=r"((r)[2]), "=r"((r)[3]) : "r"(addr))
#define MMA(acc, A, b0, b1) \
    asm volatile("mma.sync.aligned.m16n8k16.row.col.f32.bf16.bf16.f32 " \
        "{%0,%1,%2,%3}, {%4,%5,%6,%7}, {%8,%9}, {%0,%1,%2,%3};" \
        : "+f"((acc)[0]), "+f"((acc)[1]), "+f"((acc)[2]), "+f"((acc)[3]) \
        : "r"((A)[0]), "r"((A)[1]), "r"((A)[2]), "r"((A)[3]), \
          "r"(b0), "r"(b1))

__device__ __forceinline__ void cpa(uint32_t s, const bf16* g) {
    asm volatile("cp.async.cg.shared.global [%0], [%1], 16;" :: "r"(s), "l"(g));
}
#define CP_COMMIT asm volatile("cp.async.commit_group;" ::: "memory")
#define CP_WAIT1  asm volatile("cp.async.wait_group 1;"  ::: "memory")
#define CP_WAIT0  asm volatile("cp.async.wait_group 0;"  ::: "memory")

#define ROWB  80
#define TILB  10240       // one 128-row x 32-col bf16 tile (128 * 80)

// ---------------------------------------------------------------------------
// bf16(-split) HMMA GEMM
// ---------------------------------------------------------------------------
template <int NT>
__device__ __forceinline__ void stage_load(
    const bf16* __restrict__ Ah, const bf16* __restrict__ Al, long lda,
    const bf16* __restrict__ Bh, const bf16* __restrict__ Bl, long ldb,
    int bm, int bn, int k0, uint32_t sb, int tid)
{
    const uint32_t boff = (NT == 3 ? 2u : 1u) * TILB;
#pragma unroll
    for (int rep = 0; rep < 2; rep++) {
        int ci  = tid + rep * 256;
        int row = ci >> 2, c = ci & 3;
        uint32_t so = row * ROWB + c * 16;
        size_t ga = (size_t)(bm + row) * lda + k0 + c * 8;
        size_t gb = (size_t)(bn + row) * ldb + k0 + c * 8;
        cpa(sb + so,        Ah + ga);
        cpa(sb + boff + so, Bh + gb);
        if (NT == 3) {
            cpa(sb + TILB + so,        Al + ga);
            cpa(sb + boff + TILB + so, Bl + gb);
        }
    }
}

template <int NT>
__global__ __launch_bounds__(256)
void gemm_bf16(const bf16* __restrict__ Ah, const bf16* __restrict__ Al, long lda,
               const bf16* __restrict__ Bh, const bf16* __restrict__ Bl, long ldb,
               float* __restrict__ C, long ldc, int K)
{
    constexpr uint32_t STG  = (NT == 3 ? 4u : 2u) * TILB;
    constexpr uint32_t BOFF = (NT == 3 ? 2u : 1u) * TILB;

    extern __shared__ char smdyn[];
    const uint32_t sbase = smem_u32(smdyn);
    const int tid = threadIdx.x, lane = tid & 31, wid = tid >> 5;
    const int wm = wid >> 2, wn = wid & 3;

    const int bn = blockIdx.x * 128, bm = blockIdx.y * 128;

    float acc[4][4][4];
#pragma unroll
    for (int i = 0; i < 4; i++)
#pragma unroll
        for (int j = 0; j < 4; j++)
#pragma unroll
            for (int r = 0; r < 4; r++) acc[i][j][r] = 0.0f;

    stage_load<NT>(Ah, Al, lda, Bh, Bl, ldb, bm, bn, 0, sbase, tid);
    CP_COMMIT;

    const int NC = K >> 5;
    for (int c = 0; c < NC; c++) {
        CP_WAIT0;
        __syncthreads();
        if (c + 1 < NC) {
            stage_load<NT>(Ah, Al, lda, Bh, Bl, ldb, bm, bn, (c + 1) << 5,
                           sbase + ((c + 1) & 1) * STG, tid);
            CP_COMMIT;
        }

        const uint32_t ab = sbase + (c & 1) * STG;
#pragma unroll
        for (int ks = 0; ks < 2; ks++) {
            const int kb = ks * 32;
            uint32_t A_h[4][4], A_l[4][4], B_h[2][4], B_l[2][4];
#pragma unroll
            for (int mt = 0; mt < 4; mt++) {
                uint32_t ra = ab + (wm * 64 + mt * 16 + (lane & 15)) * ROWB
                                 + kb + (lane >> 4) * 16;
                LDSM4(A_h[mt], ra);
                if (NT == 3) LDSM4(A_l[mt], ra + TILB);
            }
#pragma unroll
            for (int np = 0; np < 2; np++) {
                uint32_t rb = ab + BOFF
                                 + (wn * 32 + np * 16 + (lane & 7) + ((lane >> 4) << 3)) * ROWB
                                 + kb + ((lane >> 3) & 1) * 16;
                LDSM4(B_h[np], rb);
                if (NT == 3) LDSM4(B_l[np], rb + TILB);
            }
#pragma unroll
            for (int t = 0; t < NT; t++) {
                const uint32_t (*Af)[4] = (t == 2) ? A_l : A_h;
                const uint32_t (*Bf)[4] = (t == 1) ? B_l : B_h;
#pragma unroll
                for (int mt = 0; mt < 4; mt++)
#pragma unroll
                    for (int nt = 0; nt < 4; nt++) {
                        const int np = nt >> 1, o = (nt & 1) * 2;
                        MMA(acc[mt][nt], Af[mt], Bf[np][o], Bf[np][o + 1]);
                    }
            }
        }
        __syncthreads();
    }

    const int rw = bm + wm * 64 + (lane >> 2);
    const int cw = bn + wn * 32 + (lane & 3) * 2;
#pragma unroll
    for (int mt = 0; mt < 4; mt++) {
#pragma unroll
        for (int nt = 0; nt < 4; nt++) {
            size_t r0 = rw + mt * 16;
            size_t c0 = cw + nt * 8;
            *(float2*)&C[r0 * ldc + c0] = make_float2(acc[mt][nt][0], acc[mt][nt][1]);
            *(float2*)&C[(r0 + 8) * ldc + c0] = make_float2(acc[mt][nt][2], acc[mt][nt][3]);
        }
    }
}

// ---------------------------------------------------------------------------
// Fused flash attention: S = scale*Q@K^T + mask, online softmax, out = P@V.
// CTA = 128 q-rows of one head. 8 warps stacked in M (16 rows x 128 cols each).
// Smem (120 KB total, SINGLE K buffer):
//   Q resident (4 subtiles), K single buffer (4 subtiles),
//   V^T hi/lo streamed in 32-s-col chunks (2 chunk buffers x 2 terms).
// K(s+1) prefetch into the single K buffer is issued at PV j=2, which is
// >=2 __syncthreads after every thread finished reading K(s) -> safe.
// Group ledger: preamble {Q,K0}; each s: +{ch0} WAIT1 (retires K prefetch);
// j=0,1: WAIT0 +{ch_{j+1}}; j=2: WAIT0 +{ch3} +{K(s+1) or empty}; j=3: WAIT1.
// ---------------------------------------------------------------------------
#define SQ_OFF  0
#define SK_OFF  (4 * TILB)
#define SV_OFF  (8 * TILB)                     // + buf*2*TILB + term*TILB
#define FLASH_SMEM (12 * TILB)                 // 122880 B

__device__ __forceinline__ void load_tile128(uint32_t dst, const bf16* __restrict__ g, int tid)
{
#pragma unroll
    for (int i = 0; i < 8; i++) {
        int ci = tid + i * 256;
        int row = ci >> 4, cc = ci & 15;
        cpa(dst + (cc >> 2) * TILB + row * ROWB + (cc & 3) * 16, g + row * HDD + cc * 8);
    }
}
__device__ __forceinline__ void load_vchunk(uint32_t dst, const bf16* __restrict__ vh,
                                            const bf16* __restrict__ vl, int s0, int tid)
{
#pragma unroll
    for (int i = 0; i < 2; i++) {
        int ci = tid + i * 256;
        int row = ci >> 2, c = ci & 3;
        uint32_t off = row * ROWB + c * 16;
        cpa(dst + off,        vh + (size_t)row * TT + s0 + c * 8);
        cpa(dst + TILB + off, vl + (size_t)row * TT + s0 + c * 8);
    }
}

__device__ __forceinline__ uint32_t packbf2(float lo, float hi) {
    uint32_t r;
    asm("cvt.rn.bf16x2.f32 %0, %2, %1;" : "=r"(r) : "f"(lo), "f"(hi));
    return r;
}

__global__ __launch_bounds__(256)
void flash_attn(const bf16* __restrict__ Qg, const bf16* __restrict__ Kg,
                const bf16* __restrict__ Vh, const bf16* __restrict__ Vl,
                const float* __restrict__ mask,
                bf16* __restrict__ Ohi, bf16* __restrict__ Olo, float scale)
{
    extern __shared__ char smdyn[];
    const uint32_t sb = smem_u32(smdyn);
    const int tid = threadIdx.x, lane = tid & 31, wid = tid >> 5;
    const int g = lane >> 2, t4 = lane & 3;
    const int h = blockIdx.x & 15;
    const int bm = (blockIdx.x >> 4) * 128;

    const bf16* Qh = Qg + ((size_t)h * TT + bm) * HDD;
    const bf16* Kh = Kg + (size_t)h * TT * HDD;
    const bf16* Vht = Vh + (size_t)h * HDD * TT;
    const bf16* Vlt = Vl + (size_t)h * HDD * TT;

    load_tile128(sb + SQ_OFF, Qh, tid);
    load_tile128(sb + SK_OFF, Kh, tid);
    CP_COMMIT;

    float oacc[16][4];
#pragma unroll
    for (int i = 0; i < 16; i++)
#pragma unroll
        for (int r = 0; r < 4; r++) oacc[i][r] = 0.0f;
    float m0 = -INFINITY, m1 = -INFINITY, l0 = 0.0f, l1 = 0.0f;

    const int row0 = bm + wid * 16 + g;

    for (int s = 0; s < 32; s++) {
        const uint32_t kbuf = sb + SK_OFF;           // single K buffer
        load_vchunk(sb + SV_OFF, Vht, Vlt, s * 128, tid);
        CP_COMMIT;
        CP_WAIT1;                                    // K(s) (and Q at s=0) done
        __syncthreads();

        // ---- S = Q @ K(s)^T ----
        float Sa[16][4];
#pragma unroll
        for (int i = 0; i < 16; i++)
#pragma unroll
            for (int r = 0; r < 4; r++) Sa[i][r] = 0.0f;
#pragma unroll
        for (int ks = 0; ks < 8; ks++) {
            uint32_t Aq[4];
            uint32_t ra = sb + SQ_OFF + (ks >> 1) * TILB
                          + (wid * 16 + (lane & 15)) * ROWB + (ks & 1) * 32 + (lane >> 4) * 16;
            LDSM4(Aq, ra);
#pragma unroll
            for (int np = 0; np < 8; np++) {
                uint32_t Bk[4];
                uint32_t rb = kbuf + (ks >> 1) * TILB
                              + (np * 16 + (lane & 7) + ((lane >> 4) << 3)) * ROWB
                              + (ks & 1) * 32 + ((lane >> 3) & 1) * 16;
                LDSM4(Bk, rb);
                MMA(Sa[2 * np],     Aq, Bk[0], Bk[1]);
                MMA(Sa[2 * np + 1], Aq, Bk[2], Bk[3]);
            }
        }

        // ---- scale + mask, online softmax ----
        {
            const float* mr0 = mask + (size_t)row0 * TT + s * 128 + t4 * 2;
            const float* mr1 = mr0 + 8 * TT;
            float mx0 = -INFINITY, mx1 = -INFINITY;
#pragma unroll
            for (int nt = 0; nt < 16; nt++) {
                float2 ma = *(const float2*)(mr0 + nt * 8);
                float2 mb = *(const float2*)(mr1 + nt * 8);
                Sa[nt][0] = fmaf(Sa[nt][0], scale, ma.x);
                Sa[nt][1] = fmaf(Sa[nt][1], scale, ma.y);
                Sa[nt][2] = fmaf(Sa[nt][2], scale, mb.x);
                Sa[nt][3] = fmaf(Sa[nt][3], scale, mb.y);
                mx0 = fmaxf(mx0, fmaxf(Sa[nt][0], Sa[nt][1]));
                mx1 = fmaxf(mx1, fmaxf(Sa[nt][2], Sa[nt][3]));
            }
            mx0 = fmaxf(mx0, __shfl_xor_sync(0xFFFFFFFFu, mx0, 1));
            mx0 = fmaxf(mx0, __shfl_xor_sync(0xFFFFFFFFu, mx0, 2));
            mx1 = fmaxf(mx1, __shfl_xor_sync(0xFFFFFFFFu, mx1, 1));
            mx1 = fmaxf(mx1, __shfl_xor_sync(0xFFFFFFFFu, mx1, 2));
            float mn0 = fmaxf(m0, mx0), mn1 = fmaxf(m1, mx1);
            float f0 = __expf(m0 - mn0), f1 = __expf(m1 - mn1);
            m0 = mn0; m1 = mn1;
            float s0 = 0.0f, s1 = 0.0f;
#pragma unroll
            for (int nt = 0; nt < 16; nt++) {
                Sa[nt][0] = __expf(Sa[nt][0] - m0); s0 += Sa[nt][0];
                Sa[nt][1] = __expf(Sa[nt][1] - m0); s0 += Sa[nt][1];
                Sa[nt][2] = __expf(Sa[nt][2] - m1); s1 += Sa[nt][2];
                Sa[nt][3] = __expf(Sa[nt][3] - m1); s1 += Sa[nt][3];
            }
            s0 += __shfl_xor_sync(0xFFFFFFFFu, s0, 1);
            s0 += __shfl_xor_sync(0xFFFFFFFFu, s0, 2);
            s1 += __shfl_xor_sync(0xFFFFFFFFu, s1, 1);
            s1 += __shfl_xor_sync(0xFFFFFFFFu, s1, 2);
            l0 = l0 * f0 + s0;
            l1 = l1 * f1 + s1;
#pragma unroll
            for (int nt = 0; nt < 16; nt++) {
                oacc[nt][0] *= f0; oacc[nt][1] *= f0;
                oacc[nt][2] *= f1; oacc[nt][3] *= f1;
            }
        }

        // ---- PV over 4 V chunks ----
#pragma unroll
        for (int j = 0; j < 4; j++) {
            if (j < 3) { CP_WAIT0; } else { CP_WAIT1; }
            __syncthreads();
            if (j < 2) {
                load_vchunk(sb + SV_OFF + ((j + 1) & 1) * 2 * TILB, Vht, Vlt,
                            s * 128 + (j + 1) * 32, tid);
                CP_COMMIT;
            } else if (j == 2) {
                load_vchunk(sb + SV_OFF + ((j + 1) & 1) * 2 * TILB, Vht, Vlt,
                            s * 128 + (j + 1) * 32, tid);
                CP_COMMIT;
                if (s + 1 < 32) load_tile128(sb + SK_OFF,
                                             Kh + (size_t)(s + 1) * 128 * HDD, tid);
                CP_COMMIT;   // unconditional: empty group at s=31 keeps ledger shape
            }
            const uint32_t vcb = sb + SV_OFF + (j & 1) * 2 * TILB;
#pragma unroll
            for (int kk = 0; kk < 2; kk++) {
                const int ksp = j * 2 + kk;
                uint32_t Pah[4], Pal[4];
                {
                    const float* p0 = Sa[2 * ksp];
                    const float* p1 = Sa[2 * ksp + 1];
                    float h00 = __bfloat162float(__float2bfloat16_rn(p0[0]));
                    float h01 = __bfloat162float(__float2bfloat16_rn(p0[1]));
                    float h02 = __bfloat162float(__float2bfloat16_rn(p0[2]));
                    float h03 = __bfloat162float(__float2bfloat16_rn(p0[3]));
                    float h10 = __bfloat162float(__float2bfloat16_rn(p1[0]));
                    float h11 = __bfloat162float(__float2bfloat16_rn(p1[1]));
                    float h12 = __bfloat162float(__float2bfloat16_rn(p1[2]));
                    float h13 = __bfloat162float(__float2bfloat16_rn(p1[3]));
                    Pah[0] = packbf2(h00, h01); Pah[1] = packbf2(h02, h03);
                    Pah[2] = packbf2(h10, h11); Pah[3] = packbf2(h12, h13);
                    Pal[0] = packbf2(p0[0] - h00, p0[1] - h01);
                    Pal[1] = packbf2(p0[2] - h02, p0[3] - h03);
                    Pal[2] = packbf2(p1[0] - h10, p1[1] - h11);
                    Pal[3] = packbf2(p1[2] - h12, p1[3] - h13);
                }
#pragma unroll
                for (int np = 0; np < 8; np++) {
                    uint32_t Bv[4], Bw[4];
                    uint32_t rb = vcb + (np * 16 + (lane & 7) + ((lane >> 4) << 3)) * ROWB
                                  + kk * 32 + ((lane >> 3) & 1) * 16;
                    LDSM4(Bv, rb);            // V hi
                    LDSM4(Bw, rb + TILB);     // V lo
                    MMA(oacc[2 * np],     Pah, Bv[0], Bv[1]);
                    MMA(oacc[2 * np + 1], Pah, Bv[2], Bv[3]);
                    MMA(oacc[2 * np],     Pal, Bv[0], Bv[1]);
                    MMA(oacc[2 * np + 1], Pal, Bv[2], Bv[3]);
                    MMA(oacc[2 * np],     Pah, Bw[0], Bw[1]);
                    MMA(oacc[2 * np + 1], Pah, Bw[2], Bw[3]);
                }
            }
        }
    }

    // ---- epilogue: normalize, split, store ----
    const float inv0 = 1.0f / l0, inv1 = 1.0f / l1;
    const size_t r0 = row0, r1 = row0 + 8;
#pragma unroll
    for (int nt = 0; nt < 16; nt++) {
        const size_t col = (size_t)h * HDD + nt * 8 + t4 * 2;
        bf16 a, b, c, d;
        split2(oacc[nt][0] * inv0, a, b); split2(oacc[nt][1] * inv0, c, d);
        *(__nv_bfloat162*)&Ohi[r0 * DD + col] = __nv_bfloat162(a, c);
        *(__nv_bfloat162*)&Olo[r0 * DD + col] = __nv_bfloat162(b, d);
        split2(oacc[nt][2] * inv1, a, b); split2(oacc[nt][3] * inv1, c, d);
        *(__nv_bfloat162*)&Ohi[r1 * DD + col] = __nv_bfloat162(a, c);
        *(__nv_bfloat162*)&Olo[r1 * DD + col] = __nv_bfloat162(b, d);
    }
}

// ---------------------------------------------------------------------------
// Elementwise kernels
// ---------------------------------------------------------------------------
__global__ __launch_bounds__(256)
void split_arr(const float* __restrict__ src, bf16* __restrict__ oh, bf16* __restrict__ ol)
{
    size_t i = ((size_t)blockIdx.x * 256 + threadIdx.x) * 4;
    float4 v = *(const float4*)&src[i];
    bf16 h0, l0, h1, l1, h2, l2, h3, l3;
    split2(v.x, h0, l0); split2(v.y, h1, l1); split2(v.z, h2, l2); split2(v.w, h3, l3);
    __nv_bfloat162* ph = (__nv_bfloat162*)&oh[i];
    __nv_bfloat162* pl = (__nv_bfloat162*)&ol[i];
    ph[0] = __nv_bfloat162(h0, h1); ph[1] = __nv_bfloat162(h2, h3);
    pl[0] = __nv_bfloat162(l0, l1); pl[1] = __nv_bfloat162(l2, l3);
}

__global__ __launch_bounds__(256)
void transpose_split(const float* __restrict__ W, int K, int N,
                     bf16* __restrict__ Th, bf16* __restrict__ Tl)
{
    __shared__ float tile[32][33];
    const int n0 = blockIdx.x * 32, k0 = blockIdx.y * 32;
    const int tx = threadIdx.x, ty = threadIdx.y;
#pragma unroll
    for (int j = 0; j < 4; j++)
        tile[ty + j * 8][tx] = W[(size_t)(k0 + ty + j * 8) * N + n0 + tx];
    __syncthreads();
#pragma unroll
    for (int j = 0; j < 4; j++) {
        float v = tile[tx][ty + j * 8];
        bf16 h, l; split2(v, h, l);
        size_t o = (size_t)(n0 + ty + j * 8) * K + k0 + tx;
        Th[o] = h; Tl[o] = l;
    }
}

__global__ __launch_bounds__(256)
void l2norm_bf16(const float* __restrict__ qkv,
                 bf16* __restrict__ qh, bf16* __restrict__ kh)
{
    int gw = (blockIdx.x * 256 + threadIdx.x) >> 5;
    int lane = threadIdx.x & 31;
    int part = gw / (TT * HH);
    int rem  = gw % (TT * HH);
    int t = rem / HH, h = rem % HH;
    const float* src = qkv + (size_t)t * D3 + part * DD + h * HDD;
    float4 v = *(const float4*)&src[lane * 4];
    float ss = v.x * v.x + v.y * v.y + v.z * v.z + v.w * v.w;
#pragma unroll
    for (int o = 16; o; o >>= 1) ss += __shfl_xor_sync(0xFFFFFFFFu, ss, o);
    float s = 1.0f / fmaxf(sqrtf(ss), 1e-12f);

    size_t o = ((size_t)h * TT + t) * HDD + lane * 4;
    bf16* dh = (part == 0 ? qh : kh) + o;
    ((__nv_bfloat162*)dh)[0] = __nv_bfloat162(__float2bfloat16_rn(v.x * s),
                                              __float2bfloat16_rn(v.y * s));
    ((__nv_bfloat162*)dh)[1] = __nv_bfloat162(__float2bfloat16_rn(v.z * s),
                                              __float2bfloat16_rn(v.w * s));
}

__global__ __launch_bounds__(256)
void vtrans_split(const float* __restrict__ qkv,
                  bf16* __restrict__ vth, bf16* __restrict__ vtl)
{
    __shared__ float tile[32][33];
    const int h = blockIdx.z;
    const int t0 = blockIdx.x * 32, d0 = blockIdx.y * 32;
    const int tx = threadIdx.x, ty = threadIdx.y;
#pragma unroll
    for (int j = 0; j < 4; j++)
        tile[ty + j * 8][tx] = qkv[(size_t)(t0 + ty + j * 8) * D3 + 2 * DD + h * HDD + d0 + tx];
    __syncthreads();
#pragma unroll
    for (int j = 0; j < 4; j++) {
        float v = tile[tx][ty + j * 8];
        bf16 hh, ll; split2(v, hh, ll);
        size_t o = ((size_t)h * HDD + d0 + ty + j * 8) * TT + t0 + tx;
        vth[o] = hh; vtl[o] = ll;
    }
}

// ---------------------------------------------------------------------------
// Launch
// ---------------------------------------------------------------------------
extern "C" void kernel_launch(void* const* d_in, const int* in_sizes, int n_in,
                              void* d_out, int out_size)
{
    const float* x    = (const float*)d_in[0];
    const float* mask = (const float*)d_in[1];
    const float* Wqkv = (const float*)d_in[2];
    const float* Wout = (const float*)d_in[3];
    float* out = (float*)d_out;

    float *qkv;
    bf16 *xh, *xl, *wqh, *wql, *woh, *wol, *qh, *kh, *vth, *vtl, *ah, *al;
    cudaGetSymbolAddress((void**)&qkv, g_qkv);
    cudaGetSymbolAddress((void**)&xh,  g_xh);   cudaGetSymbolAddress((void**)&xl,  g_xl);
    cudaGetSymbolAddress((void**)&wqh, g_wqh);  cudaGetSymbolAddress((void**)&wql, g_wql);
    cudaGetSymbolAddress((void**)&woh, g_woh);  cudaGetSymbolAddress((void**)&wol, g_wol);
    cudaGetSymbolAddress((void**)&qh,  g_qh);   cudaGetSymbolAddress((void**)&kh,  g_kh);
    cudaGetSymbolAddress((void**)&vth, g_vth);  cudaGetSymbolAddress((void**)&vtl, g_vtl);
    cudaGetSymbolAddress((void**)&ah,  g_ah);   cudaGetSymbolAddress((void**)&al,  g_al);

    const int SM3 = 2 * 4 * TILB;
    const int SM1 = 2 * 2 * TILB;
    cudaFuncSetAttribute(gemm_bf16<3>, cudaFuncAttributeMaxDynamicSharedMemorySize, SM3);
    cudaFuncSetAttribute(gemm_bf16<1>, cudaFuncAttributeMaxDynamicSharedMemorySize, SM1);
    cudaFuncSetAttribute(flash_attn, cudaFuncAttributeMaxDynamicSharedMemorySize, FLASH_SMEM);

    const float scale = 0.08838834764831845f;   // 1/sqrt(128)
    dim3 blk(256);
    dim3 tblk(32, 8);

    split_arr<<<(TT * DD) / 1024, blk>>>(x, xh, xl);
    transpose_split<<<dim3(D3 / 32, DD / 32), tblk>>>(Wqkv, DD, D3, wqh, wql);
    transpose_split<<<dim3(DD / 32, DD / 32), tblk>>>(Wout, DD, DD, woh, wol);

    // qkv: q,k cols 1-term; v cols 3-term
    gemm_bf16<1><<<dim3(2 * DD / 128, TT / 128), blk, SM1>>>(
        xh, nullptr, DD, wqh, nullptr, DD, qkv, D3, DD);
    gemm_bf16<3><<<dim3(DD / 128, TT / 128), blk, SM3>>>(
        xh, xl, DD, wqh + (size_t)2 * DD * DD, wql + (size_t)2 * DD * DD, DD,
        qkv + 2 * DD, D3, DD);

    l2norm_bf16<<<(2 * TT * HH) / 8, blk>>>(qkv, qh, kh);
    vtrans_split<<<dim3(TT / 32, HDD / 32, HH), tblk>>>(qkv, vth, vtl);

    // fused S + softmax + PV
    flash_attn<<<HH * (TT / 128), blk, FLASH_SMEM>>>(
        qh, kh, vth, vtl, mask, ah, al, scale);

    // out-proj
    gemm_bf16<3><<<dim3(DD / 128, TT / 128), blk, SM3>>>(
        ah, al, DD, woh, wol, DD, out, DD, DD);
}